// round 8
// baseline (speedup 1.0000x reference)
#include <cuda_runtime.h>
#include <cuda_bf16.h>
#include <math.h>

#define B_  8
#define T_  2048
#define E_  256
#define H_  8
#define D_  32
// SCALING * log2(e): scores come out pre-multiplied for exp2-based softmax
#define SCALING_L2E 0.25503540f
#define LOG2E 1.4426950408889634f

// Scratch (device globals; no allocation allowed)
__device__ __nv_bfloat16 g_q [B_*H_*T_*D_];  // [b][h][t][d]  (pre-scaled by /sqrt(d)*log2e)
__device__ __nv_bfloat16 g_k [B_*H_*T_*D_];  // [b][h][t][d]
__device__ __nv_bfloat16 g_vt[B_*H_*D_*T_];  // [b][h][d][t]
__device__ float g_ao[B_*T_*E_];             // [b][t][h*32+d]
__device__ int   g_maskflag;

// ---------------------------------------------------------------------------
__global__ void flag_init_kernel() { g_maskflag = 0; }

__global__ void mask_scan_kernel(const float* __restrict__ mask, int n4) {
    bool nz = false;
    int idx = blockIdx.x * blockDim.x + threadIdx.x;
    int stride = gridDim.x * blockDim.x;
    const float4* m4 = (const float4*)mask;
    for (int i = idx; i < n4; i += stride) {
        float4 v = m4[i];
        nz |= (v.x != 0.f) | (v.y != 0.f) | (v.z != 0.f) | (v.w != 0.f);
    }
    if (__syncthreads_or(nz)) {
        if (threadIdx.x == 0) atomicOr(&g_maskflag, 1);
    }
}

// ---------------------------------------------------------------------------
__device__ __forceinline__ unsigned packbf(float x, float y) {
    __nv_bfloat162 h = __floats2bfloat162_rn(x, y);
    return *(unsigned*)&h;
}
__device__ __forceinline__ float ex2(float x) {
    float r;
    asm("ex2.approx.ftz.f32 %0, %1;" : "=f"(r) : "f"(x));
    return r;
}
__device__ __forceinline__ void mma_bf16(float c[4], const unsigned a[4],
                                         unsigned b0, unsigned b1) {
    asm volatile(
        "mma.sync.aligned.m16n8k16.row.col.f32.bf16.bf16.f32 "
        "{%0,%1,%2,%3},{%4,%5,%6,%7},{%8,%9},{%0,%1,%2,%3};"
        : "+f"(c[0]), "+f"(c[1]), "+f"(c[2]), "+f"(c[3])
        : "r"(a[0]), "r"(a[1]), "r"(a[2]), "r"(a[3]), "r"(b0), "r"(b1));
}
__device__ __forceinline__ void ldsm4(unsigned& r0, unsigned& r1,
                                      unsigned& r2, unsigned& r3,
                                      unsigned addr) {
    asm volatile("ldmatrix.sync.aligned.m8n8.x4.shared.b16 {%0,%1,%2,%3}, [%4];"
                 : "=r"(r0), "=r"(r1), "=r"(r2), "=r"(r3) : "r"(addr));
}
__device__ __forceinline__ void cpasync16(unsigned smem, const void* gmem) {
    asm volatile("cp.async.cg.shared.global [%0], [%1], 16;"
                 :: "r"(smem), "l"(gmem));
}
// Split a float into bf16 hi + bf16 lo (residual)
__device__ __forceinline__ void bfsplit(float x, __nv_bfloat16& hi, __nv_bfloat16& lo) {
    hi = __float2bfloat16_rn(x);
    lo = __float2bfloat16_rn(x - __bfloat162float(hi));
}

// ---------------------------------------------------------------------------
// Projection GEMM: 128x128 tile, 8 warps (4m x 2n), K-chunk 32. (unchanged)
#define PSTR 40

__global__ __launch_bounds__(256) void qkv_proj_mma_kernel(
    const float* __restrict__ hs, const float* __restrict__ pos,
    const float* __restrict__ Wq, const float* __restrict__ bq,
    const float* __restrict__ Wk, const float* __restrict__ bk,
    const float* __restrict__ Wv, const float* __restrict__ bv)
{
    const int p = blockIdx.z;
    const float* W    = (p == 0) ? Wq : (p == 1) ? Wk : Wv;
    const float* bias = (p == 0) ? bq : (p == 1) ? bk : bv;

    __shared__ __nv_bfloat16 Xh[128][PSTR], Xl[128][PSTR];
    __shared__ __nv_bfloat16 Wh[128][PSTR], Wl[128][PSTR];

    const int tid  = threadIdx.x;
    const int wid  = tid >> 5;
    const int lane = tid & 31;
    const int g    = lane >> 2, q = lane & 3;
    const int wm   = wid >> 1;
    const int wn   = wid & 1;

    const int row0 = blockIdx.x * 128;
    const int col0 = blockIdx.y * 128;

    float acc[2][8][4] = {};

    for (int k0 = 0; k0 < 256; k0 += 32) {
        #pragma unroll
        for (int r = 0; r < 4; r++) {
            int i = tid + r * 256;
            int row = i >> 3, c4 = (i & 7) * 4;
            const float* src = hs + (size_t)(row0 + row) * 256 + k0 + c4;
            float4 xv = *(const float4*)src;
            if (p < 2) {
                const float* ps = pos + (size_t)(row0 + row) * 256 + k0 + c4;
                float4 pv = *(const float4*)ps;
                xv.x += pv.x; xv.y += pv.y; xv.z += pv.z; xv.w += pv.w;
            }
            __nv_bfloat16 h0,l0,h1,l1,h2,l2,h3,l3;
            bfsplit(xv.x,h0,l0); bfsplit(xv.y,h1,l1);
            bfsplit(xv.z,h2,l2); bfsplit(xv.w,h3,l3);
            __nv_bfloat162 hp0 = {h0,h1}, hp1 = {h2,h3};
            __nv_bfloat162 lp0 = {l0,l1}, lp1 = {l2,l3};
            *(uint2*)&Xh[row][c4] = make_uint2(*(unsigned*)&hp0, *(unsigned*)&hp1);
            *(uint2*)&Xl[row][c4] = make_uint2(*(unsigned*)&lp0, *(unsigned*)&lp1);
        }
        #pragma unroll
        for (int r = 0; r < 4; r++) {
            int i = tid + r * 256;
            int row = i >> 3, c4 = (i & 7) * 4;
            const float* src = W + (size_t)(col0 + row) * 256 + k0 + c4;
            float4 xv = *(const float4*)src;
            __nv_bfloat16 h0,l0,h1,l1,h2,l2,h3,l3;
            bfsplit(xv.x,h0,l0); bfsplit(xv.y,h1,l1);
            bfsplit(xv.z,h2,l2); bfsplit(xv.w,h3,l3);
            __nv_bfloat162 hp0 = {h0,h1}, hp1 = {h2,h3};
            __nv_bfloat162 lp0 = {l0,l1}, lp1 = {l2,l3};
            *(uint2*)&Wh[row][c4] = make_uint2(*(unsigned*)&hp0, *(unsigned*)&hp1);
            *(uint2*)&Wl[row][c4] = make_uint2(*(unsigned*)&lp0, *(unsigned*)&lp1);
        }
        __syncthreads();

        #pragma unroll
        for (int st = 0; st < 2; st++) {
            unsigned aH[2][4], aL[2][4];
            #pragma unroll
            for (int rc = 0; rc < 2; rc++) {
                int m = wm * 32 + rc * 16;
                aH[rc][0] = *(const unsigned*)&Xh[m + g][st*16 + 2*q];
                aH[rc][1] = *(const unsigned*)&Xh[m + g + 8][st*16 + 2*q];
                aH[rc][2] = *(const unsigned*)&Xh[m + g][st*16 + 2*q + 8];
                aH[rc][3] = *(const unsigned*)&Xh[m + g + 8][st*16 + 2*q + 8];
                aL[rc][0] = *(const unsigned*)&Xl[m + g][st*16 + 2*q];
                aL[rc][1] = *(const unsigned*)&Xl[m + g + 8][st*16 + 2*q];
                aL[rc][2] = *(const unsigned*)&Xl[m + g][st*16 + 2*q + 8];
                aL[rc][3] = *(const unsigned*)&Xl[m + g + 8][st*16 + 2*q + 8];
            }
            #pragma unroll
            for (int nc = 0; nc < 8; nc++) {
                int n = wn * 64 + nc * 8 + g;
                unsigned bH0 = *(const unsigned*)&Wh[n][st*16 + 2*q];
                unsigned bH1 = *(const unsigned*)&Wh[n][st*16 + 2*q + 8];
                unsigned bL0 = *(const unsigned*)&Wl[n][st*16 + 2*q];
                unsigned bL1 = *(const unsigned*)&Wl[n][st*16 + 2*q + 8];
                #pragma unroll
                for (int rc = 0; rc < 2; rc++) {
                    mma_bf16(acc[rc][nc], aH[rc], bH0, bH1);
                    mma_bf16(acc[rc][nc], aL[rc], bH0, bH1);
                    mma_bf16(acc[rc][nc], aH[rc], bL0, bL1);
                }
            }
        }
        __syncthreads();
    }

    #pragma unroll
    for (int nc = 0; nc < 8; nc++) {
        int col = col0 + wn * 64 + nc * 8 + 2 * q;
        float2 bv2 = *(const float2*)&bias[col];
        int h = col >> 5, d = col & 31;
        #pragma unroll
        for (int rc = 0; rc < 2; rc++) {
            int rowg = row0 + wm * 32 + rc * 16 + g;
            int bb = rowg >> 11;
            int t  = rowg & 2047;
            int bh = bb * H_ + h;
            float v0 = acc[rc][nc][0] + bv2.x;
            float v1 = acc[rc][nc][1] + bv2.y;
            float v2 = acc[rc][nc][2] + bv2.x;
            float v3 = acc[rc][nc][3] + bv2.y;
            if (p == 0) {
                *(unsigned*)&g_q[((size_t)(bh * T_ + t)) * D_ + d]     = packbf(v0 * SCALING_L2E, v1 * SCALING_L2E);
                *(unsigned*)&g_q[((size_t)(bh * T_ + t + 8)) * D_ + d] = packbf(v2 * SCALING_L2E, v3 * SCALING_L2E);
            } else if (p == 1) {
                *(unsigned*)&g_k[((size_t)(bh * T_ + t)) * D_ + d]     = packbf(v0, v1);
                *(unsigned*)&g_k[((size_t)(bh * T_ + t + 8)) * D_ + d] = packbf(v2, v3);
            } else {
                __nv_bfloat16* vd0 = g_vt + ((size_t)(bh * D_ + d)) * T_;
                __nv_bfloat16* vd1 = g_vt + ((size_t)(bh * D_ + d + 1)) * T_;
                vd0[t]     = __float2bfloat16(v0);
                vd1[t]     = __float2bfloat16(v1);
                vd0[t + 8] = __float2bfloat16(v2);
                vd1[t + 8] = __float2bfloat16(v3);
            }
        }
    }
}

// ---------------------------------------------------------------------------
__global__ __launch_bounds__(256) void out_proj_mma_kernel(
    const float* __restrict__ Wo, const float* __restrict__ bo,
    float* __restrict__ out)
{
    __shared__ __nv_bfloat16 Xh[128][PSTR], Xl[128][PSTR];
    __shared__ __nv_bfloat16 Wh[128][PSTR], Wl[128][PSTR];

    const int tid  = threadIdx.x;
    const int wid  = tid >> 5;
    const int lane = tid & 31;
    const int g    = lane >> 2, q = lane & 3;
    const int wm   = wid >> 1;
    const int wn   = wid & 1;

    const int row0 = blockIdx.x * 128;
    const int col0 = blockIdx.y * 128;

    float acc[2][8][4] = {};

    for (int k0 = 0; k0 < 256; k0 += 32) {
        #pragma unroll
        for (int r = 0; r < 4; r++) {
            int i = tid + r * 256;
            int row = i >> 3, c4 = (i & 7) * 4;
            float4 xv = *(const float4*)(g_ao + (size_t)(row0 + row) * 256 + k0 + c4);
            __nv_bfloat16 h0,l0,h1,l1,h2,l2,h3,l3;
            bfsplit(xv.x,h0,l0); bfsplit(xv.y,h1,l1);
            bfsplit(xv.z,h2,l2); bfsplit(xv.w,h3,l3);
            __nv_bfloat162 hp0 = {h0,h1}, hp1 = {h2,h3};
            __nv_bfloat162 lp0 = {l0,l1}, lp1 = {l2,l3};
            *(uint2*)&Xh[row][c4] = make_uint2(*(unsigned*)&hp0, *(unsigned*)&hp1);
            *(uint2*)&Xl[row][c4] = make_uint2(*(unsigned*)&lp0, *(unsigned*)&lp1);
        }
        #pragma unroll
        for (int r = 0; r < 4; r++) {
            int i = tid + r * 256;
            int row = i >> 3, c4 = (i & 7) * 4;
            float4 xv = *(const float4*)(Wo + (size_t)(col0 + row) * 256 + k0 + c4);
            __nv_bfloat16 h0,l0,h1,l1,h2,l2,h3,l3;
            bfsplit(xv.x,h0,l0); bfsplit(xv.y,h1,l1);
            bfsplit(xv.z,h2,l2); bfsplit(xv.w,h3,l3);
            __nv_bfloat162 hp0 = {h0,h1}, hp1 = {h2,h3};
            __nv_bfloat162 lp0 = {l0,l1}, lp1 = {l2,l3};
            *(uint2*)&Wh[row][c4] = make_uint2(*(unsigned*)&hp0, *(unsigned*)&hp1);
            *(uint2*)&Wl[row][c4] = make_uint2(*(unsigned*)&lp0, *(unsigned*)&lp1);
        }
        __syncthreads();

        #pragma unroll
        for (int st = 0; st < 2; st++) {
            unsigned aH[2][4], aL[2][4];
            #pragma unroll
            for (int rc = 0; rc < 2; rc++) {
                int m = wm * 32 + rc * 16;
                aH[rc][0] = *(const unsigned*)&Xh[m + g][st*16 + 2*q];
                aH[rc][1] = *(const unsigned*)&Xh[m + g + 8][st*16 + 2*q];
                aH[rc][2] = *(const unsigned*)&Xh[m + g][st*16 + 2*q + 8];
                aH[rc][3] = *(const unsigned*)&Xh[m + g + 8][st*16 + 2*q + 8];
                aL[rc][0] = *(const unsigned*)&Xl[m + g][st*16 + 2*q];
                aL[rc][1] = *(const unsigned*)&Xl[m + g + 8][st*16 + 2*q];
                aL[rc][2] = *(const unsigned*)&Xl[m + g][st*16 + 2*q + 8];
                aL[rc][3] = *(const unsigned*)&Xl[m + g + 8][st*16 + 2*q + 8];
            }
            #pragma unroll
            for (int nc = 0; nc < 8; nc++) {
                int n = wn * 64 + nc * 8 + g;
                unsigned bH0 = *(const unsigned*)&Wh[n][st*16 + 2*q];
                unsigned bH1 = *(const unsigned*)&Wh[n][st*16 + 2*q + 8];
                unsigned bL0 = *(const unsigned*)&Wl[n][st*16 + 2*q];
                unsigned bL1 = *(const unsigned*)&Wl[n][st*16 + 2*q + 8];
                #pragma unroll
                for (int rc = 0; rc < 2; rc++) {
                    mma_bf16(acc[rc][nc], aH[rc], bH0, bH1);
                    mma_bf16(acc[rc][nc], aL[rc], bH0, bH1);
                    mma_bf16(acc[rc][nc], aH[rc], bL0, bL1);
                }
            }
        }
        __syncthreads();
    }

    #pragma unroll
    for (int nc = 0; nc < 8; nc++) {
        int col = col0 + wn * 64 + nc * 8 + 2 * q;
        float2 bv2 = *(const float2*)&bo[col];
        #pragma unroll
        for (int rc = 0; rc < 2; rc++) {
            int rowg = row0 + wm * 32 + rc * 16 + g;
            float2 o0; o0.x = acc[rc][nc][0] + bv2.x; o0.y = acc[rc][nc][1] + bv2.y;
            float2 o1; o1.x = acc[rc][nc][2] + bv2.x; o1.y = acc[rc][nc][3] + bv2.y;
            *(float2*)&out[(size_t)rowg * 256 + col]       = o0;
            *(float2*)&out[(size_t)(rowg + 8) * 256 + col] = o1;
        }
    }
}

// ---------------------------------------------------------------------------
// Flash attention: bf16 mma, ldmatrix, exp2 softmax, cp.async double buffer.
// Split-tile pipeline: each 64-key tile processed as two 32-key halves so
// exp (MUFU) of one half overlaps PV mma (tensor) of the other.
#define KS_STRIDE 40   // halves
#define VS_STRIDE 72   // halves
__global__ __launch_bounds__(128, 5) void attn_mma_kernel(const float* __restrict__ mask)
{
    __shared__ __nv_bfloat16 Ksh[2][64][KS_STRIDE];  // [buf][n][d]
    __shared__ __nv_bfloat16 Vsh[2][32][VS_STRIDE];  // [buf][d][n]

    const int tid  = threadIdx.x;
    const int lane = tid & 31;
    const int w    = tid >> 5;
    const int g    = lane >> 2;
    const int q    = lane & 3;

    const int bh = blockIdx.y;
    const int b  = bh >> 3, h = bh & 7;
    const int m0 = blockIdx.x * 64;
    const int mrow = m0 + w * 16 + g;

    const __nv_bfloat16* kbase = g_k  + (size_t)bh * T_ * D_;
    const __nv_bfloat16* vbase = g_vt + (size_t)bh * D_ * T_;
    const float* mrow0 = mask + (size_t)b * T_ * T_ + (size_t)mrow * T_;
    const float* mrow1 = mrow0 + 8 * T_;
    const int flag = g_maskflag;

    // Staging index math
    const int krow = tid >> 2, kc = (tid & 3) * 8;
    const int krow2 = (tid + 128) >> 2, kc2 = ((tid + 128) & 3) * 8;
    const int vrow = tid >> 3, vc = (tid & 7) * 8;
    const int vrow2 = (tid + 128) >> 3, vc2 = ((tid + 128) & 7) * 8;

    const unsigned ksh0 = (unsigned)__cvta_generic_to_shared(&Ksh[0][0][0]);
    const unsigned vsh0 = (unsigned)__cvta_generic_to_shared(&Vsh[0][0][0]);
    const unsigned KBUF = 64 * KS_STRIDE * 2;
    const unsigned VBUF = 32 * VS_STRIDE * 2;
    const unsigned kst0 = ksh0 + (krow  * KS_STRIDE + kc ) * 2;
    const unsigned kst1 = ksh0 + (krow2 * KS_STRIDE + kc2) * 2;
    const unsigned vst0 = vsh0 + (vrow  * VS_STRIDE + vc ) * 2;
    const unsigned vst1 = vsh0 + (vrow2 * VS_STRIDE + vc2) * 2;
    const unsigned kfa = ksh0 + ((lane & 7) * KS_STRIDE + (lane >> 3) * 8) * 2;
    const unsigned vfa = vsh0 + ((lane & 7) * VS_STRIDE + (lane >> 3) * 8) * 2;

    // Q fragments (loop-invariant; pre-scaled by log2e/sqrt(d))
    unsigned aQ[2][4];
    {
        const __nv_bfloat16* qb = g_q + ((size_t)(bh * T_ + m0 + w * 16)) * D_;
        #pragma unroll
        for (int s = 0; s < 2; s++) {
            aQ[s][0] = *(const unsigned*)&qb[g * D_ + s * 16 + 2 * q];
            aQ[s][1] = *(const unsigned*)&qb[(g + 8) * D_ + s * 16 + 2 * q];
            aQ[s][2] = *(const unsigned*)&qb[g * D_ + s * 16 + 2 * q + 8];
            aQ[s][3] = *(const unsigned*)&qb[(g + 8) * D_ + s * 16 + 2 * q + 8];
        }
    }

    float o[4][4] = {};
    float lr0 = 0.f, lr1 = 0.f;

    // Prologue: stage tile 0 into buffer 0 via cp.async
    cpasync16(kst0, &kbase[(size_t)krow  * D_ + kc]);
    cpasync16(kst1, &kbase[(size_t)krow2 * D_ + kc2]);
    cpasync16(vst0, &vbase[(size_t)vrow  * T_ + vc]);
    cpasync16(vst1, &vbase[(size_t)vrow2 * T_ + vc2]);
    asm volatile("cp.async.commit_group;");
    asm volatile("cp.async.wait_group 0;");
    __syncthreads();

    const int NT = T_ / 64;
    for (int it = 0; it < NT; it++) {
        const int cur = it & 1;
        const unsigned nxtoff = (cur ^ 1);
        const int n0 = it * 64;

        // Kick off next tile's async copies (overlap with compute below)
        if (it + 1 < NT) {
            int nn = n0 + 64;
            cpasync16(kst0 + nxtoff * KBUF, &kbase[(size_t)(nn + krow)  * D_ + kc]);
            cpasync16(kst1 + nxtoff * KBUF, &kbase[(size_t)(nn + krow2) * D_ + kc2]);
            cpasync16(vst0 + nxtoff * VBUF, &vbase[(size_t)vrow  * T_ + nn + vc]);
            cpasync16(vst1 + nxtoff * VBUF, &vbase[(size_t)vrow2 * T_ + nn + vc2]);
            asm volatile("cp.async.commit_group;");
        }

        unsigned pA[4][4];
        float s[4][4];

        // ===== Half A: keys n0..n0+31 (j = 0..3) =====
        if (flag) {
            #pragma unroll
            for (int j = 0; j < 4; j++) {
                float2 a01 = *(const float2*)(mrow0 + n0 + j * 8 + 2 * q);
                float2 a23 = *(const float2*)(mrow1 + n0 + j * 8 + 2 * q);
                s[j][0] = a01.x * LOG2E; s[j][1] = a01.y * LOG2E;
                s[j][2] = a23.x * LOG2E; s[j][3] = a23.y * LOG2E;
            }
        } else {
            #pragma unroll
            for (int j = 0; j < 4; j++)
                #pragma unroll
                for (int c = 0; c < 4; c++) s[j][c] = 0.f;
        }
        #pragma unroll
        for (int j = 0; j < 4; j++) {
            unsigned b0, b1, b2, b3;
            ldsm4(b0, b1, b2, b3, kfa + cur * KBUF + j * 8 * KS_STRIDE * 2);
            mma_bf16(s[j], aQ[0], b0, b1);
            mma_bf16(s[j], aQ[1], b2, b3);
        }
        #pragma unroll
        for (int j = 0; j < 4; j++) {
            s[j][0] = ex2(s[j][0]);
            s[j][1] = ex2(s[j][1]);
            s[j][2] = ex2(s[j][2]);
            s[j][3] = ex2(s[j][3]);
            lr0 += s[j][0] + s[j][1];
            lr1 += s[j][2] + s[j][3];
        }
        pA[0][0] = packbf(s[0][0], s[0][1]); pA[0][1] = packbf(s[0][2], s[0][3]);
        pA[0][2] = packbf(s[1][0], s[1][1]); pA[0][3] = packbf(s[1][2], s[1][3]);
        pA[1][0] = packbf(s[2][0], s[2][1]); pA[1][1] = packbf(s[2][2], s[2][3]);
        pA[1][2] = packbf(s[3][0], s[3][1]); pA[1][3] = packbf(s[3][2], s[3][3]);

        // ===== Half B scores: keys n0+32..n0+63 (j = 4..7) =====
        if (flag) {
            #pragma unroll
            for (int j = 0; j < 4; j++) {
                float2 a01 = *(const float2*)(mrow0 + n0 + 32 + j * 8 + 2 * q);
                float2 a23 = *(const float2*)(mrow1 + n0 + 32 + j * 8 + 2 * q);
                s[j][0] = a01.x * LOG2E; s[j][1] = a01.y * LOG2E;
                s[j][2] = a23.x * LOG2E; s[j][3] = a23.y * LOG2E;
            }
        } else {
            #pragma unroll
            for (int j = 0; j < 4; j++)
                #pragma unroll
                for (int c = 0; c < 4; c++) s[j][c] = 0.f;
        }
        #pragma unroll
        for (int j = 0; j < 4; j++) {
            unsigned b0, b1, b2, b3;
            ldsm4(b0, b1, b2, b3, kfa + cur * KBUF + (j + 4) * 8 * KS_STRIDE * 2);
            mma_bf16(s[j], aQ[0], b0, b1);
            mma_bf16(s[j], aQ[1], b2, b3);
        }

        // ===== PV half A (tensor) — independent of half-B exp (MUFU) =====
        #pragma unroll
        for (int t = 0; t < 4; t++) {
            unsigned v0, v1, v2, v3;
            ldsm4(v0, v1, v2, v3, vfa + cur * VBUF + t * 8 * VS_STRIDE * 2);
            mma_bf16(o[t], pA[0], v0, v1);
            mma_bf16(o[t], pA[1], v2, v3);
        }

        // ===== Half B exp + pack =====
        #pragma unroll
        for (int j = 0; j < 4; j++) {
            s[j][0] = ex2(s[j][0]);
            s[j][1] = ex2(s[j][1]);
            s[j][2] = ex2(s[j][2]);
            s[j][3] = ex2(s[j][3]);
            lr0 += s[j][0] + s[j][1];
            lr1 += s[j][2] + s[j][3];
        }
        pA[2][0] = packbf(s[0][0], s[0][1]); pA[2][1] = packbf(s[0][2], s[0][3]);
        pA[2][2] = packbf(s[1][0], s[1][1]); pA[2][3] = packbf(s[1][2], s[1][3]);
        pA[3][0] = packbf(s[2][0], s[2][1]); pA[3][1] = packbf(s[2][2], s[2][3]);
        pA[3][2] = packbf(s[3][0], s[3][1]); pA[3][3] = packbf(s[3][2], s[3][3]);

        // ===== PV half B =====
        #pragma unroll
        for (int t = 0; t < 4; t++) {
            unsigned v4, v5, v6, v7;
            ldsm4(v4, v5, v6, v7, vfa + cur * VBUF + t * 8 * VS_STRIDE * 2 + 32 * 2);
            mma_bf16(o[t], pA[2], v4, v5);
            mma_bf16(o[t], pA[3], v6, v7);
        }

        if (it + 1 < NT) {
            asm volatile("cp.async.wait_group 0;");
            __syncthreads();
        }
    }

    // Deferred quad reduction of the softmax sums
    lr0 += __shfl_xor_sync(0xffffffffu, lr0, 1);
    lr0 += __shfl_xor_sync(0xffffffffu, lr0, 2);
    lr1 += __shfl_xor_sync(0xffffffffu, lr1, 1);
    lr1 += __shfl_xor_sync(0xffffffffu, lr1, 2);

    float inv0 = 1.f / lr0, inv1 = 1.f / lr1;
    float* dst0 = g_ao + ((size_t)(b * T_ + mrow)) * E_ + h * 32;
    float* dst1 = dst0 + 8 * E_;
    #pragma unroll
    for (int t = 0; t < 4; t++) {
        int dd = t * 8 + 2 * q;
        float2 v0; v0.x = o[t][0] * inv0; v0.y = o[t][1] * inv0;
        float2 v1; v1.x = o[t][2] * inv1; v1.y = o[t][3] * inv1;
        *(float2*)&dst0[dd] = v0;
        *(float2*)&dst1[dd] = v1;
    }
}

// ---------------------------------------------------------------------------
extern "C" void kernel_launch(void* const* d_in, const int* in_sizes, int n_in,
                              void* d_out, int out_size)
{
    const float* hs   = (const float*)d_in[0];
    const float* pos  = (const float*)d_in[1];
    const float* mask = (const float*)d_in[2];
    const float* Wq   = (const float*)d_in[3];
    const float* bq   = (const float*)d_in[4];
    const float* Wk   = (const float*)d_in[5];
    const float* bk   = (const float*)d_in[6];
    const float* Wv   = (const float*)d_in[7];
    const float* bv   = (const float*)d_in[8];
    const float* Wo   = (const float*)d_in[9];
    const float* bo   = (const float*)d_in[10];
    float* out = (float*)d_out;

    flag_init_kernel<<<1, 1>>>();
    mask_scan_kernel<<<1024, 256>>>(mask, (B_ * T_ * T_) / 4);

    dim3 pgrid(B_ * T_ / 128, E_ / 128, 3);
    qkv_proj_mma_kernel<<<pgrid, 256>>>(hs, pos, Wq, bq, Wk, bk, Wv, bv);

    dim3 agrid(T_ / 64, B_ * H_);
    attn_mma_kernel<<<agrid, 128>>>(mask);

    dim3 ogrid(B_ * T_ / 128, E_ / 128);
    out_proj_mma_kernel<<<ogrid, 256>>>(Wo, bo, out);
}

// round 9
// speedup vs baseline: 1.0360x; 1.0360x over previous
#include <cuda_runtime.h>
#include <cuda_bf16.h>
#include <math.h>

#define B_  8
#define T_  2048
#define E_  256
#define H_  8
#define D_  32
// SCALING * log2(e): scores come out pre-multiplied for exp2-based softmax
#define SCALING_L2E 0.25503540f
#define LOG2E 1.4426950408889634f

// Scratch (device globals; no allocation allowed)
__device__ __nv_bfloat16 g_q [B_*T_*E_];     // per-head [b][h][t][d]
__device__ __nv_bfloat16 g_k [B_*T_*E_];
__device__ __nv_bfloat16 g_vt[B_*T_*E_];     // [b][h][d][t]
__device__ __nv_bfloat16 g_xqk_h[B_*T_*E_], g_xqk_l[B_*T_*E_];  // hs+pos split
__device__ __nv_bfloat16 g_xv_h [B_*T_*E_], g_xv_l [B_*T_*E_];  // hs split
__device__ __nv_bfloat16 g_wh[4*E_*E_], g_wl[4*E_*E_];           // Wq,Wk,Wv,Wo split
__device__ __nv_bfloat16 g_ao_h[B_*T_*E_], g_ao_l[B_*T_*E_];     // attn out split
__device__ int   g_maskflag;

// ---------------------------------------------------------------------------
__global__ void flag_init_kernel() { g_maskflag = 0; }

__global__ void mask_scan_kernel(const float* __restrict__ mask, int n4) {
    bool nz = false;
    int idx = blockIdx.x * blockDim.x + threadIdx.x;
    int stride = gridDim.x * blockDim.x;
    const float4* m4 = (const float4*)mask;
    for (int i = idx; i < n4; i += stride) {
        float4 v = m4[i];
        nz |= (v.x != 0.f) | (v.y != 0.f) | (v.z != 0.f) | (v.w != 0.f);
    }
    if (__syncthreads_or(nz)) {
        if (threadIdx.x == 0) atomicOr(&g_maskflag, 1);
    }
}

// ---------------------------------------------------------------------------
__device__ __forceinline__ unsigned packbf(float x, float y) {
    __nv_bfloat162 h = __floats2bfloat162_rn(x, y);
    return *(unsigned*)&h;
}
__device__ __forceinline__ float ex2(float x) {
    float r;
    asm("ex2.approx.ftz.f32 %0, %1;" : "=f"(r) : "f"(x));
    return r;
}
__device__ __forceinline__ void mma_bf16(float c[4], const unsigned a[4],
                                         unsigned b0, unsigned b1) {
    asm volatile(
        "mma.sync.aligned.m16n8k16.row.col.f32.bf16.bf16.f32 "
        "{%0,%1,%2,%3},{%4,%5,%6,%7},{%8,%9},{%0,%1,%2,%3};"
        : "+f"(c[0]), "+f"(c[1]), "+f"(c[2]), "+f"(c[3])
        : "r"(a[0]), "r"(a[1]), "r"(a[2]), "r"(a[3]), "r"(b0), "r"(b1));
}
__device__ __forceinline__ void ldsm4(unsigned& r0, unsigned& r1,
                                      unsigned& r2, unsigned& r3,
                                      unsigned addr) {
    asm volatile("ldmatrix.sync.aligned.m8n8.x4.shared.b16 {%0,%1,%2,%3}, [%4];"
                 : "=r"(r0), "=r"(r1), "=r"(r2), "=r"(r3) : "r"(addr));
}
__device__ __forceinline__ void cpasync16(unsigned smem, const void* gmem) {
    asm volatile("cp.async.cg.shared.global [%0], [%1], 16;"
                 :: "r"(smem), "l"(gmem));
}
__device__ __forceinline__ void bfsplit(float x, __nv_bfloat16& hi, __nv_bfloat16& lo) {
    hi = __float2bfloat16_rn(x);
    lo = __float2bfloat16_rn(x - __bfloat162float(hi));
}
// split 4 floats -> two uint2 (hi pair-packed, lo pair-packed)
__device__ __forceinline__ void split4(float4 v, uint2& hi, uint2& lo) {
    __nv_bfloat16 h0,l0,h1,l1,h2,l2,h3,l3;
    bfsplit(v.x,h0,l0); bfsplit(v.y,h1,l1);
    bfsplit(v.z,h2,l2); bfsplit(v.w,h3,l3);
    __nv_bfloat162 hp0 = {h0,h1}, hp1 = {h2,h3};
    __nv_bfloat162 lp0 = {l0,l1}, lp1 = {l2,l3};
    hi = make_uint2(*(unsigned*)&hp0, *(unsigned*)&hp1);
    lo = make_uint2(*(unsigned*)&lp0, *(unsigned*)&lp1);
}

// ---------------------------------------------------------------------------
// Pre-pass: split hs+pos (qk input) and hs (v input) into global bf16 hi/lo.
__global__ __launch_bounds__(256) void split_x_kernel(
    const float* __restrict__ hs, const float* __restrict__ pos)
{
    int i = blockIdx.x * 256 + threadIdx.x;       // float4 index
    float4 a = ((const float4*)hs)[i];
    float4 p = ((const float4*)pos)[i];
    uint2 hi, lo;
    split4(a, hi, lo);
    *(uint2*)&g_xv_h[i * 4] = hi;
    *(uint2*)&g_xv_l[i * 4] = lo;
    a.x += p.x; a.y += p.y; a.z += p.z; a.w += p.w;
    split4(a, hi, lo);
    *(uint2*)&g_xqk_h[i * 4] = hi;
    *(uint2*)&g_xqk_l[i * 4] = lo;
}

// Pre-pass: split the 4 weight matrices.
__global__ __launch_bounds__(256) void split_w_kernel(
    const float* __restrict__ Wq, const float* __restrict__ Wk,
    const float* __restrict__ Wv, const float* __restrict__ Wo)
{
    int z = blockIdx.y;
    const float* W = (z == 0) ? Wq : (z == 1) ? Wk : (z == 2) ? Wv : Wo;
    int i = blockIdx.x * 256 + threadIdx.x;       // float4 index within matrix
    float4 v = ((const float4*)W)[i];
    uint2 hi, lo;
    split4(v, hi, lo);
    *(uint2*)&g_wh[z * E_ * E_ + i * 4] = hi;
    *(uint2*)&g_wl[z * E_ * E_ + i * 4] = lo;
}

// ---------------------------------------------------------------------------
// GEMM core: 128x128 tile, 8 warps (4m x 2n), K-chunk 32, pre-split bf16 in,
// cp.async staging, 3-term split MMA.
#define PSTR 40

// MMA inner block shared by both GEMM kernels (expects sXh/sXl/sWh/sWl in scope)
#define GEMM_MMA_CHUNK()                                                      \
    _Pragma("unroll")                                                         \
    for (int st = 0; st < 2; st++) {                                          \
        unsigned aH[2][4], aL[2][4];                                          \
        _Pragma("unroll")                                                     \
        for (int rc = 0; rc < 2; rc++) {                                      \
            int m = wm * 32 + rc * 16;                                        \
            aH[rc][0] = *(const unsigned*)&sXh[m + g][st*16 + 2*q];           \
            aH[rc][1] = *(const unsigned*)&sXh[m + g + 8][st*16 + 2*q];       \
            aH[rc][2] = *(const unsigned*)&sXh[m + g][st*16 + 2*q + 8];       \
            aH[rc][3] = *(const unsigned*)&sXh[m + g + 8][st*16 + 2*q + 8];   \
            aL[rc][0] = *(const unsigned*)&sXl[m + g][st*16 + 2*q];           \
            aL[rc][1] = *(const unsigned*)&sXl[m + g + 8][st*16 + 2*q];       \
            aL[rc][2] = *(const unsigned*)&sXl[m + g][st*16 + 2*q + 8];       \
            aL[rc][3] = *(const unsigned*)&sXl[m + g + 8][st*16 + 2*q + 8];   \
        }                                                                     \
        _Pragma("unroll")                                                     \
        for (int nc = 0; nc < 8; nc++) {                                      \
            int n = wn * 64 + nc * 8 + g;                                     \
            unsigned bH0 = *(const unsigned*)&sWh[n][st*16 + 2*q];            \
            unsigned bH1 = *(const unsigned*)&sWh[n][st*16 + 2*q + 8];        \
            unsigned bL0 = *(const unsigned*)&sWl[n][st*16 + 2*q];            \
            unsigned bL1 = *(const unsigned*)&sWl[n][st*16 + 2*q + 8];        \
            _Pragma("unroll")                                                 \
            for (int rc = 0; rc < 2; rc++) {                                  \
                mma_bf16(acc[rc][nc], aH[rc], bH0, bH1);                      \
                mma_bf16(acc[rc][nc], aL[rc], bH0, bH1);                      \
                mma_bf16(acc[rc][nc], aH[rc], bL0, bL1);                      \
            }                                                                 \
        }                                                                     \
    }

__global__ __launch_bounds__(256) void qkv_gemm_kernel(
    const float* __restrict__ bq, const float* __restrict__ bk,
    const float* __restrict__ bv)
{
    const int p = blockIdx.z;
    const __nv_bfloat16* Xh = (p < 2) ? g_xqk_h : g_xv_h;
    const __nv_bfloat16* Xl = (p < 2) ? g_xqk_l : g_xv_l;
    const __nv_bfloat16* Wh = g_wh + p * E_ * E_;
    const __nv_bfloat16* Wl = g_wl + p * E_ * E_;
    const float* bias = (p == 0) ? bq : (p == 1) ? bk : bv;

    __shared__ __nv_bfloat16 sXh[128][PSTR], sXl[128][PSTR];
    __shared__ __nv_bfloat16 sWh[128][PSTR], sWl[128][PSTR];

    const int tid  = threadIdx.x;
    const int wid  = tid >> 5;
    const int lane = tid & 31;
    const int g    = lane >> 2, q = lane & 3;
    const int wm   = wid >> 1, wn = wid & 1;

    const int row0 = blockIdx.x * 128;
    const int col0 = blockIdx.y * 128;

    // Staging indices: 2 (row,seg) tasks per thread per array
    const int r0_ = tid >> 2, s0_ = (tid & 3) * 8;
    const int r1_ = (tid + 256) >> 2, s1_ = ((tid + 256) & 3) * 8;
    const unsigned bXh = (unsigned)__cvta_generic_to_shared(&sXh[0][0]);
    const unsigned bXl = (unsigned)__cvta_generic_to_shared(&sXl[0][0]);
    const unsigned bWh = (unsigned)__cvta_generic_to_shared(&sWh[0][0]);
    const unsigned bWl = (unsigned)__cvta_generic_to_shared(&sWl[0][0]);

    float acc[2][8][4] = {};

    for (int k0 = 0; k0 < 256; k0 += 32) {
        cpasync16(bXh + (r0_*PSTR + s0_)*2, &Xh[(size_t)(row0 + r0_)*256 + k0 + s0_]);
        cpasync16(bXh + (r1_*PSTR + s1_)*2, &Xh[(size_t)(row0 + r1_)*256 + k0 + s1_]);
        cpasync16(bXl + (r0_*PSTR + s0_)*2, &Xl[(size_t)(row0 + r0_)*256 + k0 + s0_]);
        cpasync16(bXl + (r1_*PSTR + s1_)*2, &Xl[(size_t)(row0 + r1_)*256 + k0 + s1_]);
        cpasync16(bWh + (r0_*PSTR + s0_)*2, &Wh[(size_t)(col0 + r0_)*256 + k0 + s0_]);
        cpasync16(bWh + (r1_*PSTR + s1_)*2, &Wh[(size_t)(col0 + r1_)*256 + k0 + s1_]);
        cpasync16(bWl + (r0_*PSTR + s0_)*2, &Wl[(size_t)(col0 + r0_)*256 + k0 + s0_]);
        cpasync16(bWl + (r1_*PSTR + s1_)*2, &Wl[(size_t)(col0 + r1_)*256 + k0 + s1_]);
        asm volatile("cp.async.commit_group;");
        asm volatile("cp.async.wait_group 0;");
        __syncthreads();

        GEMM_MMA_CHUNK();
        __syncthreads();
    }

    // Epilogue: bias + scatter to bf16 per-head layouts
    #pragma unroll
    for (int nc = 0; nc < 8; nc++) {
        int col = col0 + wn * 64 + nc * 8 + 2 * q;
        float2 bv2 = *(const float2*)&bias[col];
        int h = col >> 5, d = col & 31;
        #pragma unroll
        for (int rc = 0; rc < 2; rc++) {
            int rowg = row0 + wm * 32 + rc * 16 + g;
            int bb = rowg >> 11;
            int t  = rowg & 2047;
            int bh = bb * H_ + h;
            float v0 = acc[rc][nc][0] + bv2.x;
            float v1 = acc[rc][nc][1] + bv2.y;
            float v2 = acc[rc][nc][2] + bv2.x;
            float v3 = acc[rc][nc][3] + bv2.y;
            if (p == 0) {
                *(unsigned*)&g_q[((size_t)(bh * T_ + t)) * D_ + d]     = packbf(v0 * SCALING_L2E, v1 * SCALING_L2E);
                *(unsigned*)&g_q[((size_t)(bh * T_ + t + 8)) * D_ + d] = packbf(v2 * SCALING_L2E, v3 * SCALING_L2E);
            } else if (p == 1) {
                *(unsigned*)&g_k[((size_t)(bh * T_ + t)) * D_ + d]     = packbf(v0, v1);
                *(unsigned*)&g_k[((size_t)(bh * T_ + t + 8)) * D_ + d] = packbf(v2, v3);
            } else {
                __nv_bfloat16* vd0 = g_vt + ((size_t)(bh * D_ + d)) * T_;
                __nv_bfloat16* vd1 = g_vt + ((size_t)(bh * D_ + d + 1)) * T_;
                vd0[t]     = __float2bfloat16(v0);
                vd1[t]     = __float2bfloat16(v1);
                vd0[t + 8] = __float2bfloat16(v2);
                vd1[t + 8] = __float2bfloat16(v3);
            }
        }
    }
}

__global__ __launch_bounds__(256) void out_gemm_kernel(
    const float* __restrict__ bo, float* __restrict__ out)
{
    const __nv_bfloat16* Xh = g_ao_h;
    const __nv_bfloat16* Xl = g_ao_l;
    const __nv_bfloat16* Wh = g_wh + 3 * E_ * E_;
    const __nv_bfloat16* Wl = g_wl + 3 * E_ * E_;

    __shared__ __nv_bfloat16 sXh[128][PSTR], sXl[128][PSTR];
    __shared__ __nv_bfloat16 sWh[128][PSTR], sWl[128][PSTR];

    const int tid  = threadIdx.x;
    const int wid  = tid >> 5;
    const int lane = tid & 31;
    const int g    = lane >> 2, q = lane & 3;
    const int wm   = wid >> 1, wn = wid & 1;

    const int row0 = blockIdx.x * 128;
    const int col0 = blockIdx.y * 128;

    const int r0_ = tid >> 2, s0_ = (tid & 3) * 8;
    const int r1_ = (tid + 256) >> 2, s1_ = ((tid + 256) & 3) * 8;
    const unsigned bXh = (unsigned)__cvta_generic_to_shared(&sXh[0][0]);
    const unsigned bXl = (unsigned)__cvta_generic_to_shared(&sXl[0][0]);
    const unsigned bWh = (unsigned)__cvta_generic_to_shared(&sWh[0][0]);
    const unsigned bWl = (unsigned)__cvta_generic_to_shared(&sWl[0][0]);

    float acc[2][8][4] = {};

    for (int k0 = 0; k0 < 256; k0 += 32) {
        cpasync16(bXh + (r0_*PSTR + s0_)*2, &Xh[(size_t)(row0 + r0_)*256 + k0 + s0_]);
        cpasync16(bXh + (r1_*PSTR + s1_)*2, &Xh[(size_t)(row0 + r1_)*256 + k0 + s1_]);
        cpasync16(bXl + (r0_*PSTR + s0_)*2, &Xl[(size_t)(row0 + r0_)*256 + k0 + s0_]);
        cpasync16(bXl + (r1_*PSTR + s1_)*2, &Xl[(size_t)(row0 + r1_)*256 + k0 + s1_]);
        cpasync16(bWh + (r0_*PSTR + s0_)*2, &Wh[(size_t)(col0 + r0_)*256 + k0 + s0_]);
        cpasync16(bWh + (r1_*PSTR + s1_)*2, &Wh[(size_t)(col0 + r1_)*256 + k0 + s1_]);
        cpasync16(bWl + (r0_*PSTR + s0_)*2, &Wl[(size_t)(col0 + r0_)*256 + k0 + s0_]);
        cpasync16(bWl + (r1_*PSTR + s1_)*2, &Wl[(size_t)(col0 + r1_)*256 + k0 + s1_]);
        asm volatile("cp.async.commit_group;");
        asm volatile("cp.async.wait_group 0;");
        __syncthreads();

        GEMM_MMA_CHUNK();
        __syncthreads();
    }

    #pragma unroll
    for (int nc = 0; nc < 8; nc++) {
        int col = col0 + wn * 64 + nc * 8 + 2 * q;
        float2 bv2 = *(const float2*)&bo[col];
        #pragma unroll
        for (int rc = 0; rc < 2; rc++) {
            int rowg = row0 + wm * 32 + rc * 16 + g;
            float2 o0; o0.x = acc[rc][nc][0] + bv2.x; o0.y = acc[rc][nc][1] + bv2.y;
            float2 o1; o1.x = acc[rc][nc][2] + bv2.x; o1.y = acc[rc][nc][3] + bv2.y;
            *(float2*)&out[(size_t)rowg * 256 + col]       = o0;
            *(float2*)&out[(size_t)(rowg + 8) * 256 + col] = o1;
        }
    }
}

// ---------------------------------------------------------------------------
// Flash attention (unchanged from R8 except epilogue writes split bf16).
#define KS_STRIDE 40   // halves
#define VS_STRIDE 72   // halves
__global__ __launch_bounds__(128, 5) void attn_mma_kernel(const float* __restrict__ mask)
{
    __shared__ __nv_bfloat16 Ksh[2][64][KS_STRIDE];
    __shared__ __nv_bfloat16 Vsh[2][32][VS_STRIDE];

    const int tid  = threadIdx.x;
    const int lane = tid & 31;
    const int w    = tid >> 5;
    const int g    = lane >> 2;
    const int q    = lane & 3;

    const int bh = blockIdx.y;
    const int b  = bh >> 3, h = bh & 7;
    const int m0 = blockIdx.x * 64;
    const int mrow = m0 + w * 16 + g;

    const __nv_bfloat16* kbase = g_k  + (size_t)bh * T_ * D_;
    const __nv_bfloat16* vbase = g_vt + (size_t)bh * D_ * T_;
    const float* mrow0 = mask + (size_t)b * T_ * T_ + (size_t)mrow * T_;
    const float* mrow1 = mrow0 + 8 * T_;
    const int flag = g_maskflag;

    const int krow = tid >> 2, kc = (tid & 3) * 8;
    const int krow2 = (tid + 128) >> 2, kc2 = ((tid + 128) & 3) * 8;
    const int vrow = tid >> 3, vc = (tid & 7) * 8;
    const int vrow2 = (tid + 128) >> 3, vc2 = ((tid + 128) & 7) * 8;

    const unsigned ksh0 = (unsigned)__cvta_generic_to_shared(&Ksh[0][0][0]);
    const unsigned vsh0 = (unsigned)__cvta_generic_to_shared(&Vsh[0][0][0]);
    const unsigned KBUF = 64 * KS_STRIDE * 2;
    const unsigned VBUF = 32 * VS_STRIDE * 2;
    const unsigned kst0 = ksh0 + (krow  * KS_STRIDE + kc ) * 2;
    const unsigned kst1 = ksh0 + (krow2 * KS_STRIDE + kc2) * 2;
    const unsigned vst0 = vsh0 + (vrow  * VS_STRIDE + vc ) * 2;
    const unsigned vst1 = vsh0 + (vrow2 * VS_STRIDE + vc2) * 2;
    const unsigned kfa = ksh0 + ((lane & 7) * KS_STRIDE + (lane >> 3) * 8) * 2;
    const unsigned vfa = vsh0 + ((lane & 7) * VS_STRIDE + (lane >> 3) * 8) * 2;

    unsigned aQ[2][4];
    {
        const __nv_bfloat16* qb = g_q + ((size_t)(bh * T_ + m0 + w * 16)) * D_;
        #pragma unroll
        for (int s = 0; s < 2; s++) {
            aQ[s][0] = *(const unsigned*)&qb[g * D_ + s * 16 + 2 * q];
            aQ[s][1] = *(const unsigned*)&qb[(g + 8) * D_ + s * 16 + 2 * q];
            aQ[s][2] = *(const unsigned*)&qb[g * D_ + s * 16 + 2 * q + 8];
            aQ[s][3] = *(const unsigned*)&qb[(g + 8) * D_ + s * 16 + 2 * q + 8];
        }
    }

    float o[4][4] = {};
    float lr0 = 0.f, lr1 = 0.f;

    cpasync16(kst0, &kbase[(size_t)krow  * D_ + kc]);
    cpasync16(kst1, &kbase[(size_t)krow2 * D_ + kc2]);
    cpasync16(vst0, &vbase[(size_t)vrow  * T_ + vc]);
    cpasync16(vst1, &vbase[(size_t)vrow2 * T_ + vc2]);
    asm volatile("cp.async.commit_group;");
    asm volatile("cp.async.wait_group 0;");
    __syncthreads();

    const int NT = T_ / 64;
    for (int it = 0; it < NT; it++) {
        const int cur = it & 1;
        const unsigned nxtoff = (cur ^ 1);
        const int n0 = it * 64;

        if (it + 1 < NT) {
            int nn = n0 + 64;
            cpasync16(kst0 + nxtoff * KBUF, &kbase[(size_t)(nn + krow)  * D_ + kc]);
            cpasync16(kst1 + nxtoff * KBUF, &kbase[(size_t)(nn + krow2) * D_ + kc2]);
            cpasync16(vst0 + nxtoff * VBUF, &vbase[(size_t)vrow  * T_ + nn + vc]);
            cpasync16(vst1 + nxtoff * VBUF, &vbase[(size_t)vrow2 * T_ + nn + vc2]);
            asm volatile("cp.async.commit_group;");
        }

        unsigned pA[4][4];
        float s[4][4];

        // Half A
        if (flag) {
            #pragma unroll
            for (int j = 0; j < 4; j++) {
                float2 a01 = *(const float2*)(mrow0 + n0 + j * 8 + 2 * q);
                float2 a23 = *(const float2*)(mrow1 + n0 + j * 8 + 2 * q);
                s[j][0] = a01.x * LOG2E; s[j][1] = a01.y * LOG2E;
                s[j][2] = a23.x * LOG2E; s[j][3] = a23.y * LOG2E;
            }
        } else {
            #pragma unroll
            for (int j = 0; j < 4; j++)
                #pragma unroll
                for (int c = 0; c < 4; c++) s[j][c] = 0.f;
        }
        #pragma unroll
        for (int j = 0; j < 4; j++) {
            unsigned b0, b1, b2, b3;
            ldsm4(b0, b1, b2, b3, kfa + cur * KBUF + j * 8 * KS_STRIDE * 2);
            mma_bf16(s[j], aQ[0], b0, b1);
            mma_bf16(s[j], aQ[1], b2, b3);
        }
        #pragma unroll
        for (int j = 0; j < 4; j++) {
            s[j][0] = ex2(s[j][0]); s[j][1] = ex2(s[j][1]);
            s[j][2] = ex2(s[j][2]); s[j][3] = ex2(s[j][3]);
            lr0 += s[j][0] + s[j][1];
            lr1 += s[j][2] + s[j][3];
        }
        pA[0][0] = packbf(s[0][0], s[0][1]); pA[0][1] = packbf(s[0][2], s[0][3]);
        pA[0][2] = packbf(s[1][0], s[1][1]); pA[0][3] = packbf(s[1][2], s[1][3]);
        pA[1][0] = packbf(s[2][0], s[2][1]); pA[1][1] = packbf(s[2][2], s[2][3]);
        pA[1][2] = packbf(s[3][0], s[3][1]); pA[1][3] = packbf(s[3][2], s[3][3]);

        // Half B scores
        if (flag) {
            #pragma unroll
            for (int j = 0; j < 4; j++) {
                float2 a01 = *(const float2*)(mrow0 + n0 + 32 + j * 8 + 2 * q);
                float2 a23 = *(const float2*)(mrow1 + n0 + 32 + j * 8 + 2 * q);
                s[j][0] = a01.x * LOG2E; s[j][1] = a01.y * LOG2E;
                s[j][2] = a23.x * LOG2E; s[j][3] = a23.y * LOG2E;
            }
        } else {
            #pragma unroll
            for (int j = 0; j < 4; j++)
                #pragma unroll
                for (int c = 0; c < 4; c++) s[j][c] = 0.f;
        }
        #pragma unroll
        for (int j = 0; j < 4; j++) {
            unsigned b0, b1, b2, b3;
            ldsm4(b0, b1, b2, b3, kfa + cur * KBUF + (j + 4) * 8 * KS_STRIDE * 2);
            mma_bf16(s[j], aQ[0], b0, b1);
            mma_bf16(s[j], aQ[1], b2, b3);
        }

        // PV half A
        #pragma unroll
        for (int t = 0; t < 4; t++) {
            unsigned v0, v1, v2, v3;
            ldsm4(v0, v1, v2, v3, vfa + cur * VBUF + t * 8 * VS_STRIDE * 2);
            mma_bf16(o[t], pA[0], v0, v1);
            mma_bf16(o[t], pA[1], v2, v3);
        }

        // Half B exp + pack
        #pragma unroll
        for (int j = 0; j < 4; j++) {
            s[j][0] = ex2(s[j][0]); s[j][1] = ex2(s[j][1]);
            s[j][2] = ex2(s[j][2]); s[j][3] = ex2(s[j][3]);
            lr0 += s[j][0] + s[j][1];
            lr1 += s[j][2] + s[j][3];
        }
        pA[2][0] = packbf(s[0][0], s[0][1]); pA[2][1] = packbf(s[0][2], s[0][3]);
        pA[2][2] = packbf(s[1][0], s[1][1]); pA[2][3] = packbf(s[1][2], s[1][3]);
        pA[3][0] = packbf(s[2][0], s[2][1]); pA[3][1] = packbf(s[2][2], s[2][3]);
        pA[3][2] = packbf(s[3][0], s[3][1]); pA[3][3] = packbf(s[3][2], s[3][3]);

        // PV half B
        #pragma unroll
        for (int t = 0; t < 4; t++) {
            unsigned v4, v5, v6, v7;
            ldsm4(v4, v5, v6, v7, vfa + cur * VBUF + t * 8 * VS_STRIDE * 2 + 32 * 2);
            mma_bf16(o[t], pA[2], v4, v5);
            mma_bf16(o[t], pA[3], v6, v7);
        }

        if (it + 1 < NT) {
            asm volatile("cp.async.wait_group 0;");
            __syncthreads();
        }
    }

    lr0 += __shfl_xor_sync(0xffffffffu, lr0, 1);
    lr0 += __shfl_xor_sync(0xffffffffu, lr0, 2);
    lr1 += __shfl_xor_sync(0xffffffffu, lr1, 1);
    lr1 += __shfl_xor_sync(0xffffffffu, lr1, 2);

    // Epilogue: normalize, write split bf16 to g_ao_h/g_ao_l
    float inv0 = 1.f / lr0, inv1 = 1.f / lr1;
    size_t base0 = ((size_t)(b * T_ + mrow)) * E_ + h * 32;
    size_t base1 = base0 + 8 * E_;
    #pragma unroll
    for (int t = 0; t < 4; t++) {
        int dd = t * 8 + 2 * q;
        float x0 = o[t][0] * inv0, x1 = o[t][1] * inv0;
        float y0 = o[t][2] * inv1, y1 = o[t][3] * inv1;
        __nv_bfloat16 h0,l0,h1,l1;
        bfsplit(x0,h0,l0); bfsplit(x1,h1,l1);
        __nv_bfloat162 hp = {h0,h1}, lp = {l0,l1};
        *(unsigned*)&g_ao_h[base0 + dd] = *(unsigned*)&hp;
        *(unsigned*)&g_ao_l[base0 + dd] = *(unsigned*)&lp;
        bfsplit(y0,h0,l0); bfsplit(y1,h1,l1);
        __nv_bfloat162 hq = {h0,h1}, lq = {l0,l1};
        *(unsigned*)&g_ao_h[base1 + dd] = *(unsigned*)&hq;
        *(unsigned*)&g_ao_l[base1 + dd] = *(unsigned*)&lq;
    }
}

// ---------------------------------------------------------------------------
extern "C" void kernel_launch(void* const* d_in, const int* in_sizes, int n_in,
                              void* d_out, int out_size)
{
    const float* hs   = (const float*)d_in[0];
    const float* pos  = (const float*)d_in[1];
    const float* mask = (const float*)d_in[2];
    const float* Wq   = (const float*)d_in[3];
    const float* bq   = (const float*)d_in[4];
    const float* Wk   = (const float*)d_in[5];
    const float* bk   = (const float*)d_in[6];
    const float* Wv   = (const float*)d_in[7];
    const float* bv   = (const float*)d_in[8];
    const float* Wo   = (const float*)d_in[9];
    const float* bo   = (const float*)d_in[10];
    float* out = (float*)d_out;

    flag_init_kernel<<<1, 1>>>();
    mask_scan_kernel<<<1024, 256>>>(mask, (B_ * T_ * T_) / 4);

    split_x_kernel<<<(B_ * T_ * E_) / 4 / 256, 256>>>(hs, pos);
    split_w_kernel<<<dim3((E_ * E_) / 4 / 256, 4), 256>>>(Wq, Wk, Wv, Wo);

    dim3 pgrid(B_ * T_ / 128, E_ / 128, 3);
    qkv_gemm_kernel<<<pgrid, 256>>>(bq, bk, bv);

    dim3 agrid(T_ / 64, B_ * H_);
    attn_mma_kernel<<<agrid, 128>>>(mask);

    dim3 ogrid(B_ * T_ / 128, E_ / 128);
    out_gemm_kernel<<<ogrid, 256>>>(bo, out);
}

// round 10
// speedup vs baseline: 1.3208x; 1.2748x over previous
#include <cuda_runtime.h>
#include <cuda_bf16.h>
#include <cuda_fp16.h>
#include <math.h>

#define B_  8
#define T_  2048
#define E_  256
#define H_  8
#define D_  32
// SCALING * log2(e): scores come out pre-multiplied for exp2-based softmax
#define SCALING_L2E 0.25503540f
#define LOG2E 1.4426950408889634f

// Scratch (device globals; no allocation allowed)
__device__ __nv_bfloat16 g_q [B_*T_*E_];     // per-head [b][h][t][d]
__device__ __nv_bfloat16 g_k [B_*T_*E_];
__device__ __nv_bfloat16 g_vt[B_*T_*E_];     // [b][h][d][t]
__device__ __half g_xqk[B_*T_*E_];           // hs+pos fp16
__device__ __half g_xv [B_*T_*E_];           // hs fp16
__device__ __half g_w  [4*E_*E_];            // Wq,Wk,Wv,Wo fp16
__device__ __half g_ao [B_*T_*E_];           // attn out fp16
__device__ int   g_maskflag;

// ---------------------------------------------------------------------------
__global__ void flag_init_kernel() { g_maskflag = 0; }

__global__ void mask_scan_kernel(const float* __restrict__ mask, int n4) {
    bool nz = false;
    int idx = blockIdx.x * blockDim.x + threadIdx.x;
    int stride = gridDim.x * blockDim.x;
    const float4* m4 = (const float4*)mask;
    for (int i = idx; i < n4; i += stride) {
        float4 v = m4[i];
        nz |= (v.x != 0.f) | (v.y != 0.f) | (v.z != 0.f) | (v.w != 0.f);
    }
    if (__syncthreads_or(nz)) {
        if (threadIdx.x == 0) atomicOr(&g_maskflag, 1);
    }
}

// ---------------------------------------------------------------------------
__device__ __forceinline__ unsigned packbf(float x, float y) {
    __nv_bfloat162 h = __floats2bfloat162_rn(x, y);
    return *(unsigned*)&h;
}
__device__ __forceinline__ unsigned packhf(float x, float y) {
    __half2 h = __floats2half2_rn(x, y);
    return *(unsigned*)&h;
}
__device__ __forceinline__ float ex2(float x) {
    float r;
    asm("ex2.approx.ftz.f32 %0, %1;" : "=f"(r) : "f"(x));
    return r;
}
__device__ __forceinline__ void mma_bf16(float c[4], const unsigned a[4],
                                         unsigned b0, unsigned b1) {
    asm volatile(
        "mma.sync.aligned.m16n8k16.row.col.f32.bf16.bf16.f32 "
        "{%0,%1,%2,%3},{%4,%5,%6,%7},{%8,%9},{%0,%1,%2,%3};"
        : "+f"(c[0]), "+f"(c[1]), "+f"(c[2]), "+f"(c[3])
        : "r"(a[0]), "r"(a[1]), "r"(a[2]), "r"(a[3]), "r"(b0), "r"(b1));
}
__device__ __forceinline__ void mma_f16(float c[4], const unsigned a[4],
                                        unsigned b0, unsigned b1) {
    asm volatile(
        "mma.sync.aligned.m16n8k16.row.col.f32.f16.f16.f32 "
        "{%0,%1,%2,%3},{%4,%5,%6,%7},{%8,%9},{%0,%1,%2,%3};"
        : "+f"(c[0]), "+f"(c[1]), "+f"(c[2]), "+f"(c[3])
        : "r"(a[0]), "r"(a[1]), "r"(a[2]), "r"(a[3]), "r"(b0), "r"(b1));
}
__device__ __forceinline__ void ldsm4(unsigned& r0, unsigned& r1,
                                      unsigned& r2, unsigned& r3,
                                      unsigned addr) {
    asm volatile("ldmatrix.sync.aligned.m8n8.x4.shared.b16 {%0,%1,%2,%3}, [%4];"
                 : "=r"(r0), "=r"(r1), "=r"(r2), "=r"(r3) : "r"(addr));
}
__device__ __forceinline__ void cpasync16(unsigned smem, const void* gmem) {
    asm volatile("cp.async.cg.shared.global [%0], [%1], 16;"
                 :: "r"(smem), "l"(gmem));
}

// ---------------------------------------------------------------------------
// Pre-pass: convert hs+pos and hs to fp16.
__global__ __launch_bounds__(256) void split_x_kernel(
    const float* __restrict__ hs, const float* __restrict__ pos)
{
    int i = blockIdx.x * 256 + threadIdx.x;       // float4 index
    float4 a = ((const float4*)hs)[i];
    float4 p = ((const float4*)pos)[i];
    *(uint2*)&g_xv[i * 4] = make_uint2(packhf(a.x, a.y), packhf(a.z, a.w));
    a.x += p.x; a.y += p.y; a.z += p.z; a.w += p.w;
    *(uint2*)&g_xqk[i * 4] = make_uint2(packhf(a.x, a.y), packhf(a.z, a.w));
}

// Pre-pass: convert the 4 weight matrices to fp16.
__global__ __launch_bounds__(256) void split_w_kernel(
    const float* __restrict__ Wq, const float* __restrict__ Wk,
    const float* __restrict__ Wv, const float* __restrict__ Wo)
{
    int z = blockIdx.y;
    const float* W = (z == 0) ? Wq : (z == 1) ? Wk : (z == 2) ? Wv : Wo;
    int i = blockIdx.x * 256 + threadIdx.x;
    float4 v = ((const float4*)W)[i];
    *(uint2*)&g_w[z * E_ * E_ + i * 4] = make_uint2(packhf(v.x, v.y), packhf(v.z, v.w));
}

// ---------------------------------------------------------------------------
// GEMM core: 128x128 tile, 8 warps (4m x 2n), K-chunk 32, fp16 single-term,
// cp.async double-buffered K pipeline.
#define PSTR 40
#define GBUF (128 * PSTR * 2)   // bytes per smem buffer

#define GEMM_STAGE(buf, k0, X, W)                                              \
    do {                                                                       \
        cpasync16(bX + (buf) * GBUF + (r0_*PSTR + s0_)*2,                      \
                  &X[(size_t)(row0 + r0_)*256 + (k0) + s0_]);                  \
        cpasync16(bX + (buf) * GBUF + (r1_*PSTR + s1_)*2,                      \
                  &X[(size_t)(row0 + r1_)*256 + (k0) + s1_]);                  \
        cpasync16(bW + (buf) * GBUF + (r0_*PSTR + s0_)*2,                      \
                  &W[(size_t)(col0 + r0_)*256 + (k0) + s0_]);                  \
        cpasync16(bW + (buf) * GBUF + (r1_*PSTR + s1_)*2,                      \
                  &W[(size_t)(col0 + r1_)*256 + (k0) + s1_]);                  \
        asm volatile("cp.async.commit_group;");                                \
    } while (0)

#define GEMM_MMA_CHUNK(cur)                                                    \
    _Pragma("unroll")                                                          \
    for (int st = 0; st < 2; st++) {                                           \
        unsigned aF[2][4];                                                     \
        _Pragma("unroll")                                                      \
        for (int rc = 0; rc < 2; rc++) {                                       \
            int m = wm * 32 + rc * 16;                                         \
            aF[rc][0] = *(const unsigned*)&sX[cur][m + g][st*16 + 2*q];        \
            aF[rc][1] = *(const unsigned*)&sX[cur][m + g + 8][st*16 + 2*q];    \
            aF[rc][2] = *(const unsigned*)&sX[cur][m + g][st*16 + 2*q + 8];    \
            aF[rc][3] = *(const unsigned*)&sX[cur][m + g + 8][st*16 + 2*q + 8];\
        }                                                                      \
        _Pragma("unroll")                                                      \
        for (int nc = 0; nc < 8; nc++) {                                       \
            int n = wn * 64 + nc * 8 + g;                                      \
            unsigned b0 = *(const unsigned*)&sW[cur][n][st*16 + 2*q];          \
            unsigned b1 = *(const unsigned*)&sW[cur][n][st*16 + 2*q + 8];      \
            _Pragma("unroll")                                                  \
            for (int rc = 0; rc < 2; rc++)                                     \
                mma_f16(acc[rc][nc], aF[rc], b0, b1);                          \
        }                                                                      \
    }

__global__ __launch_bounds__(256) void qkv_gemm_kernel(
    const float* __restrict__ bq, const float* __restrict__ bk,
    const float* __restrict__ bv)
{
    const int p = blockIdx.z;
    const __half* X = (p < 2) ? g_xqk : g_xv;
    const __half* W = g_w + p * E_ * E_;
    const float* bias = (p == 0) ? bq : (p == 1) ? bk : bv;

    __shared__ __half sX[2][128][PSTR], sW[2][128][PSTR];

    const int tid  = threadIdx.x;
    const int wid  = tid >> 5;
    const int lane = tid & 31;
    const int g    = lane >> 2, q = lane & 3;
    const int wm   = wid >> 1, wn = wid & 1;

    const int row0 = blockIdx.x * 128;
    const int col0 = blockIdx.y * 128;

    const int r0_ = tid >> 2, s0_ = (tid & 3) * 8;
    const int r1_ = (tid + 256) >> 2, s1_ = ((tid + 256) & 3) * 8;
    const unsigned bX = (unsigned)__cvta_generic_to_shared(&sX[0][0][0]);
    const unsigned bW = (unsigned)__cvta_generic_to_shared(&sW[0][0][0]);

    float acc[2][8][4] = {};

    GEMM_STAGE(0, 0, X, W);
    #pragma unroll
    for (int kc = 0; kc < 8; kc++) {
        const int cur = kc & 1;
        if (kc + 1 < 8) GEMM_STAGE(cur ^ 1, (kc + 1) * 32, X, W);
        if (kc + 1 < 8) { asm volatile("cp.async.wait_group 1;"); }
        else            { asm volatile("cp.async.wait_group 0;"); }
        __syncthreads();
        GEMM_MMA_CHUNK(cur);
        __syncthreads();
    }

    // Epilogue: bias + scatter to bf16 per-head layouts
    #pragma unroll
    for (int nc = 0; nc < 8; nc++) {
        int col = col0 + wn * 64 + nc * 8 + 2 * q;
        float2 bv2 = *(const float2*)&bias[col];
        int h = col >> 5, d = col & 31;
        #pragma unroll
        for (int rc = 0; rc < 2; rc++) {
            int rowg = row0 + wm * 32 + rc * 16 + g;
            int bb = rowg >> 11;
            int t  = rowg & 2047;
            int bh = bb * H_ + h;
            float v0 = acc[rc][nc][0] + bv2.x;
            float v1 = acc[rc][nc][1] + bv2.y;
            float v2 = acc[rc][nc][2] + bv2.x;
            float v3 = acc[rc][nc][3] + bv2.y;
            if (p == 0) {
                *(unsigned*)&g_q[((size_t)(bh * T_ + t)) * D_ + d]     = packbf(v0 * SCALING_L2E, v1 * SCALING_L2E);
                *(unsigned*)&g_q[((size_t)(bh * T_ + t + 8)) * D_ + d] = packbf(v2 * SCALING_L2E, v3 * SCALING_L2E);
            } else if (p == 1) {
                *(unsigned*)&g_k[((size_t)(bh * T_ + t)) * D_ + d]     = packbf(v0, v1);
                *(unsigned*)&g_k[((size_t)(bh * T_ + t + 8)) * D_ + d] = packbf(v2, v3);
            } else {
                __nv_bfloat16* vd0 = g_vt + ((size_t)(bh * D_ + d)) * T_;
                __nv_bfloat16* vd1 = g_vt + ((size_t)(bh * D_ + d + 1)) * T_;
                vd0[t]     = __float2bfloat16(v0);
                vd1[t]     = __float2bfloat16(v1);
                vd0[t + 8] = __float2bfloat16(v2);
                vd1[t + 8] = __float2bfloat16(v3);
            }
        }
    }
}

__global__ __launch_bounds__(256) void out_gemm_kernel(
    const float* __restrict__ bo, float* __restrict__ out)
{
    const __half* X = g_ao;
    const __half* W = g_w + 3 * E_ * E_;

    __shared__ __half sX[2][128][PSTR], sW[2][128][PSTR];

    const int tid  = threadIdx.x;
    const int wid  = tid >> 5;
    const int lane = tid & 31;
    const int g    = lane >> 2, q = lane & 3;
    const int wm   = wid >> 1, wn = wid & 1;

    const int row0 = blockIdx.x * 128;
    const int col0 = blockIdx.y * 128;

    const int r0_ = tid >> 2, s0_ = (tid & 3) * 8;
    const int r1_ = (tid + 256) >> 2, s1_ = ((tid + 256) & 3) * 8;
    const unsigned bX = (unsigned)__cvta_generic_to_shared(&sX[0][0][0]);
    const unsigned bW = (unsigned)__cvta_generic_to_shared(&sW[0][0][0]);

    float acc[2][8][4] = {};

    GEMM_STAGE(0, 0, X, W);
    #pragma unroll
    for (int kc = 0; kc < 8; kc++) {
        const int cur = kc & 1;
        if (kc + 1 < 8) GEMM_STAGE(cur ^ 1, (kc + 1) * 32, X, W);
        if (kc + 1 < 8) { asm volatile("cp.async.wait_group 1;"); }
        else            { asm volatile("cp.async.wait_group 0;"); }
        __syncthreads();
        GEMM_MMA_CHUNK(cur);
        __syncthreads();
    }

    #pragma unroll
    for (int nc = 0; nc < 8; nc++) {
        int col = col0 + wn * 64 + nc * 8 + 2 * q;
        float2 bv2 = *(const float2*)&bo[col];
        #pragma unroll
        for (int rc = 0; rc < 2; rc++) {
            int rowg = row0 + wm * 32 + rc * 16 + g;
            float2 o0; o0.x = acc[rc][nc][0] + bv2.x; o0.y = acc[rc][nc][1] + bv2.y;
            float2 o1; o1.x = acc[rc][nc][2] + bv2.x; o1.y = acc[rc][nc][3] + bv2.y;
            *(float2*)&out[(size_t)rowg * 256 + col]       = o0;
            *(float2*)&out[(size_t)(rowg + 8) * 256 + col] = o1;
        }
    }
}

// ---------------------------------------------------------------------------
// Flash attention (unchanged from R8/R9 core; epilogue writes fp16 g_ao).
#define KS_STRIDE 40   // halves
#define VS_STRIDE 72   // halves
__global__ __launch_bounds__(128, 5) void attn_mma_kernel(const float* __restrict__ mask)
{
    __shared__ __nv_bfloat16 Ksh[2][64][KS_STRIDE];
    __shared__ __nv_bfloat16 Vsh[2][32][VS_STRIDE];

    const int tid  = threadIdx.x;
    const int lane = tid & 31;
    const int w    = tid >> 5;
    const int g    = lane >> 2;
    const int q    = lane & 3;

    const int bh = blockIdx.y;
    const int b  = bh >> 3, h = bh & 7;
    const int m0 = blockIdx.x * 64;
    const int mrow = m0 + w * 16 + g;

    const __nv_bfloat16* kbase = g_k  + (size_t)bh * T_ * D_;
    const __nv_bfloat16* vbase = g_vt + (size_t)bh * D_ * T_;
    const float* mrow0 = mask + (size_t)b * T_ * T_ + (size_t)mrow * T_;
    const float* mrow1 = mrow0 + 8 * T_;
    const int flag = g_maskflag;

    const int krow = tid >> 2, kc = (tid & 3) * 8;
    const int krow2 = (tid + 128) >> 2, kc2 = ((tid + 128) & 3) * 8;
    const int vrow = tid >> 3, vc = (tid & 7) * 8;
    const int vrow2 = (tid + 128) >> 3, vc2 = ((tid + 128) & 7) * 8;

    const unsigned ksh0 = (unsigned)__cvta_generic_to_shared(&Ksh[0][0][0]);
    const unsigned vsh0 = (unsigned)__cvta_generic_to_shared(&Vsh[0][0][0]);
    const unsigned KBUF = 64 * KS_STRIDE * 2;
    const unsigned VBUF = 32 * VS_STRIDE * 2;
    const unsigned kst0 = ksh0 + (krow  * KS_STRIDE + kc ) * 2;
    const unsigned kst1 = ksh0 + (krow2 * KS_STRIDE + kc2) * 2;
    const unsigned vst0 = vsh0 + (vrow  * VS_STRIDE + vc ) * 2;
    const unsigned vst1 = vsh0 + (vrow2 * VS_STRIDE + vc2) * 2;
    const unsigned kfa = ksh0 + ((lane & 7) * KS_STRIDE + (lane >> 3) * 8) * 2;
    const unsigned vfa = vsh0 + ((lane & 7) * VS_STRIDE + (lane >> 3) * 8) * 2;

    unsigned aQ[2][4];
    {
        const __nv_bfloat16* qb = g_q + ((size_t)(bh * T_ + m0 + w * 16)) * D_;
        #pragma unroll
        for (int s = 0; s < 2; s++) {
            aQ[s][0] = *(const unsigned*)&qb[g * D_ + s * 16 + 2 * q];
            aQ[s][1] = *(const unsigned*)&qb[(g + 8) * D_ + s * 16 + 2 * q];
            aQ[s][2] = *(const unsigned*)&qb[g * D_ + s * 16 + 2 * q + 8];
            aQ[s][3] = *(const unsigned*)&qb[(g + 8) * D_ + s * 16 + 2 * q + 8];
        }
    }

    float o[4][4] = {};
    float lr0 = 0.f, lr1 = 0.f;

    cpasync16(kst0, &kbase[(size_t)krow  * D_ + kc]);
    cpasync16(kst1, &kbase[(size_t)krow2 * D_ + kc2]);
    cpasync16(vst0, &vbase[(size_t)vrow  * T_ + vc]);
    cpasync16(vst1, &vbase[(size_t)vrow2 * T_ + vc2]);
    asm volatile("cp.async.commit_group;");
    asm volatile("cp.async.wait_group 0;");
    __syncthreads();

    const int NT = T_ / 64;
    for (int it = 0; it < NT; it++) {
        const int cur = it & 1;
        const unsigned nxtoff = (cur ^ 1);
        const int n0 = it * 64;

        if (it + 1 < NT) {
            int nn = n0 + 64;
            cpasync16(kst0 + nxtoff * KBUF, &kbase[(size_t)(nn + krow)  * D_ + kc]);
            cpasync16(kst1 + nxtoff * KBUF, &kbase[(size_t)(nn + krow2) * D_ + kc2]);
            cpasync16(vst0 + nxtoff * VBUF, &vbase[(size_t)vrow  * T_ + nn + vc]);
            cpasync16(vst1 + nxtoff * VBUF, &vbase[(size_t)vrow2 * T_ + nn + vc2]);
            asm volatile("cp.async.commit_group;");
        }

        unsigned pA[4][4];
        float s[4][4];

        // Half A
        if (flag) {
            #pragma unroll
            for (int j = 0; j < 4; j++) {
                float2 a01 = *(const float2*)(mrow0 + n0 + j * 8 + 2 * q);
                float2 a23 = *(const float2*)(mrow1 + n0 + j * 8 + 2 * q);
                s[j][0] = a01.x * LOG2E; s[j][1] = a01.y * LOG2E;
                s[j][2] = a23.x * LOG2E; s[j][3] = a23.y * LOG2E;
            }
        } else {
            #pragma unroll
            for (int j = 0; j < 4; j++)
                #pragma unroll
                for (int c = 0; c < 4; c++) s[j][c] = 0.f;
        }
        #pragma unroll
        for (int j = 0; j < 4; j++) {
            unsigned b0, b1, b2, b3;
            ldsm4(b0, b1, b2, b3, kfa + cur * KBUF + j * 8 * KS_STRIDE * 2);
            mma_bf16(s[j], aQ[0], b0, b1);
            mma_bf16(s[j], aQ[1], b2, b3);
        }
        #pragma unroll
        for (int j = 0; j < 4; j++) {
            s[j][0] = ex2(s[j][0]); s[j][1] = ex2(s[j][1]);
            s[j][2] = ex2(s[j][2]); s[j][3] = ex2(s[j][3]);
            lr0 += s[j][0] + s[j][1];
            lr1 += s[j][2] + s[j][3];
        }
        pA[0][0] = packbf(s[0][0], s[0][1]); pA[0][1] = packbf(s[0][2], s[0][3]);
        pA[0][2] = packbf(s[1][0], s[1][1]); pA[0][3] = packbf(s[1][2], s[1][3]);
        pA[1][0] = packbf(s[2][0], s[2][1]); pA[1][1] = packbf(s[2][2], s[2][3]);
        pA[1][2] = packbf(s[3][0], s[3][1]); pA[1][3] = packbf(s[3][2], s[3][3]);

        // Half B scores
        if (flag) {
            #pragma unroll
            for (int j = 0; j < 4; j++) {
                float2 a01 = *(const float2*)(mrow0 + n0 + 32 + j * 8 + 2 * q);
                float2 a23 = *(const float2*)(mrow1 + n0 + 32 + j * 8 + 2 * q);
                s[j][0] = a01.x * LOG2E; s[j][1] = a01.y * LOG2E;
                s[j][2] = a23.x * LOG2E; s[j][3] = a23.y * LOG2E;
            }
        } else {
            #pragma unroll
            for (int j = 0; j < 4; j++)
                #pragma unroll
                for (int c = 0; c < 4; c++) s[j][c] = 0.f;
        }
        #pragma unroll
        for (int j = 0; j < 4; j++) {
            unsigned b0, b1, b2, b3;
            ldsm4(b0, b1, b2, b3, kfa + cur * KBUF + (j + 4) * 8 * KS_STRIDE * 2);
            mma_bf16(s[j], aQ[0], b0, b1);
            mma_bf16(s[j], aQ[1], b2, b3);
        }

        // PV half A
        #pragma unroll
        for (int t = 0; t < 4; t++) {
            unsigned v0, v1, v2, v3;
            ldsm4(v0, v1, v2, v3, vfa + cur * VBUF + t * 8 * VS_STRIDE * 2);
            mma_bf16(o[t], pA[0], v0, v1);
            mma_bf16(o[t], pA[1], v2, v3);
        }

        // Half B exp + pack
        #pragma unroll
        for (int j = 0; j < 4; j++) {
            s[j][0] = ex2(s[j][0]); s[j][1] = ex2(s[j][1]);
            s[j][2] = ex2(s[j][2]); s[j][3] = ex2(s[j][3]);
            lr0 += s[j][0] + s[j][1];
            lr1 += s[j][2] + s[j][3];
        }
        pA[2][0] = packbf(s[0][0], s[0][1]); pA[2][1] = packbf(s[0][2], s[0][3]);
        pA[2][2] = packbf(s[1][0], s[1][1]); pA[2][3] = packbf(s[1][2], s[1][3]);
        pA[3][0] = packbf(s[2][0], s[2][1]); pA[3][1] = packbf(s[2][2], s[2][3]);
        pA[3][2] = packbf(s[3][0], s[3][1]); pA[3][3] = packbf(s[3][2], s[3][3]);

        // PV half B
        #pragma unroll
        for (int t = 0; t < 4; t++) {
            unsigned v4, v5, v6, v7;
            ldsm4(v4, v5, v6, v7, vfa + cur * VBUF + t * 8 * VS_STRIDE * 2 + 32 * 2);
            mma_bf16(o[t], pA[2], v4, v5);
            mma_bf16(o[t], pA[3], v6, v7);
        }

        if (it + 1 < NT) {
            asm volatile("cp.async.wait_group 0;");
            __syncthreads();
        }
    }

    lr0 += __shfl_xor_sync(0xffffffffu, lr0, 1);
    lr0 += __shfl_xor_sync(0xffffffffu, lr0, 2);
    lr1 += __shfl_xor_sync(0xffffffffu, lr1, 1);
    lr1 += __shfl_xor_sync(0xffffffffu, lr1, 2);

    // Epilogue: normalize, write fp16 to g_ao
    float inv0 = 1.f / lr0, inv1 = 1.f / lr1;
    size_t base0 = ((size_t)(b * T_ + mrow)) * E_ + h * 32;
    size_t base1 = base0 + 8 * E_;
    #pragma unroll
    for (int t = 0; t < 4; t++) {
        int dd = t * 8 + 2 * q;
        *(unsigned*)&g_ao[base0 + dd] = packhf(o[t][0] * inv0, o[t][1] * inv0);
        *(unsigned*)&g_ao[base1 + dd] = packhf(o[t][2] * inv1, o[t][3] * inv1);
    }
}

// ---------------------------------------------------------------------------
extern "C" void kernel_launch(void* const* d_in, const int* in_sizes, int n_in,
                              void* d_out, int out_size)
{
    const float* hs   = (const float*)d_in[0];
    const float* pos  = (const float*)d_in[1];
    const float* mask = (const float*)d_in[2];
    const float* Wq   = (const float*)d_in[3];
    const float* bq   = (const float*)d_in[4];
    const float* Wk   = (const float*)d_in[5];
    const float* bk   = (const float*)d_in[6];
    const float* Wv   = (const float*)d_in[7];
    const float* bv   = (const float*)d_in[8];
    const float* Wo   = (const float*)d_in[9];
    const float* bo   = (const float*)d_in[10];
    float* out = (float*)d_out;

    flag_init_kernel<<<1, 1>>>();
    mask_scan_kernel<<<1024, 256>>>(mask, (B_ * T_ * T_) / 4);

    split_x_kernel<<<(B_ * T_ * E_) / 4 / 256, 256>>>(hs, pos);
    split_w_kernel<<<dim3((E_ * E_) / 4 / 256, 4), 256>>>(Wq, Wk, Wv, Wo);

    dim3 pgrid(B_ * T_ / 128, E_ / 128, 3);
    qkv_gemm_kernel<<<pgrid, 256>>>(bq, bk, bv);

    dim3 agrid(T_ / 64, B_ * H_);
    attn_mma_kernel<<<agrid, 128>>>(mask);

    dim3 ogrid(B_ * T_ / 128, E_ / 128);
    out_gemm_kernel<<<ogrid, 256>>>(bo, out);
}

// round 11
// speedup vs baseline: 1.3310x; 1.0077x over previous
#include <cuda_runtime.h>
#include <cuda_bf16.h>
#include <cuda_fp16.h>
#include <math.h>

#define B_  8
#define T_  2048
#define E_  256
#define H_  8
#define D_  32
// SCALING * log2(e): scores come out pre-multiplied for exp2-based softmax
#define SCALING_L2E 0.25503540f
#define LOG2E 1.4426950408889634f

// Scratch (device globals; no allocation allowed)
__device__ __half g_q [B_*T_*E_];            // per-head [b][h][t][d], fp16
__device__ __half g_k [B_*T_*E_];
__device__ __half g_vt[B_*T_*E_];            // [b][h][d][t], fp16
__device__ __half g_xqk[B_*T_*E_];           // hs+pos fp16
__device__ __half g_xv [B_*T_*E_];           // hs fp16
__device__ __half g_w  [4*E_*E_];            // Wq,Wk,Wv,Wo fp16
__device__ __half g_ao [B_*T_*E_];           // attn out fp16
__device__ int   g_maskflag;

// ---------------------------------------------------------------------------
__global__ void flag_init_kernel() { g_maskflag = 0; }

__global__ void mask_scan_kernel(const float* __restrict__ mask, int n4) {
    bool nz = false;
    int idx = blockIdx.x * blockDim.x + threadIdx.x;
    int stride = gridDim.x * blockDim.x;
    const float4* m4 = (const float4*)mask;
    for (int i = idx; i < n4; i += stride) {
        float4 v = m4[i];
        nz |= (v.x != 0.f) | (v.y != 0.f) | (v.z != 0.f) | (v.w != 0.f);
    }
    if (__syncthreads_or(nz)) {
        if (threadIdx.x == 0) atomicOr(&g_maskflag, 1);
    }
}

// ---------------------------------------------------------------------------
__device__ __forceinline__ unsigned packhf(float x, float y) {
    __half2 h = __floats2half2_rn(x, y);
    return *(unsigned*)&h;
}
__device__ __forceinline__ unsigned ex2h2(unsigned x) {
    unsigned r;
    asm("ex2.approx.f16x2 %0, %1;" : "=r"(r) : "r"(x));
    return r;
}
__device__ __forceinline__ void mma_f16(float c[4], const unsigned a[4],
                                        unsigned b0, unsigned b1) {
    asm volatile(
        "mma.sync.aligned.m16n8k16.row.col.f32.f16.f16.f32 "
        "{%0,%1,%2,%3},{%4,%5,%6,%7},{%8,%9},{%0,%1,%2,%3};"
        : "+f"(c[0]), "+f"(c[1]), "+f"(c[2]), "+f"(c[3])
        : "r"(a[0]), "r"(a[1]), "r"(a[2]), "r"(a[3]), "r"(b0), "r"(b1));
}
__device__ __forceinline__ void ldsm4(unsigned& r0, unsigned& r1,
                                      unsigned& r2, unsigned& r3,
                                      unsigned addr) {
    asm volatile("ldmatrix.sync.aligned.m8n8.x4.shared.b16 {%0,%1,%2,%3}, [%4];"
                 : "=r"(r0), "=r"(r1), "=r"(r2), "=r"(r3) : "r"(addr));
}
__device__ __forceinline__ void cpasync16(unsigned smem, const void* gmem) {
    asm volatile("cp.async.cg.shared.global [%0], [%1], 16;"
                 :: "r"(smem), "l"(gmem));
}

// ---------------------------------------------------------------------------
// Pre-pass: convert hs+pos and hs to fp16.
__global__ __launch_bounds__(256) void split_x_kernel(
    const float* __restrict__ hs, const float* __restrict__ pos)
{
    int i = blockIdx.x * 256 + threadIdx.x;       // float4 index
    float4 a = ((const float4*)hs)[i];
    float4 p = ((const float4*)pos)[i];
    *(uint2*)&g_xv[i * 4] = make_uint2(packhf(a.x, a.y), packhf(a.z, a.w));
    a.x += p.x; a.y += p.y; a.z += p.z; a.w += p.w;
    *(uint2*)&g_xqk[i * 4] = make_uint2(packhf(a.x, a.y), packhf(a.z, a.w));
}

// Pre-pass: convert the 4 weight matrices to fp16.
__global__ __launch_bounds__(256) void split_w_kernel(
    const float* __restrict__ Wq, const float* __restrict__ Wk,
    const float* __restrict__ Wv, const float* __restrict__ Wo)
{
    int z = blockIdx.y;
    const float* W = (z == 0) ? Wq : (z == 1) ? Wk : (z == 2) ? Wv : Wo;
    int i = blockIdx.x * 256 + threadIdx.x;
    float4 v = ((const float4*)W)[i];
    *(uint2*)&g_w[z * E_ * E_ + i * 4] = make_uint2(packhf(v.x, v.y), packhf(v.z, v.w));
}

// ---------------------------------------------------------------------------
// GEMM core: 128x128 tile, 8 warps (4m x 2n), K-chunk 32, fp16 single-term,
// cp.async double-buffered K pipeline.
#define PSTR 40
#define GBUF (128 * PSTR * 2)   // bytes per smem buffer

#define GEMM_STAGE(buf, k0, X, W)                                              \
    do {                                                                       \
        cpasync16(bX + (buf) * GBUF + (r0_*PSTR + s0_)*2,                      \
                  &X[(size_t)(row0 + r0_)*256 + (k0) + s0_]);                  \
        cpasync16(bX + (buf) * GBUF + (r1_*PSTR + s1_)*2,                      \
                  &X[(size_t)(row0 + r1_)*256 + (k0) + s1_]);                  \
        cpasync16(bW + (buf) * GBUF + (r0_*PSTR + s0_)*2,                      \
                  &W[(size_t)(col0 + r0_)*256 + (k0) + s0_]);                  \
        cpasync16(bW + (buf) * GBUF + (r1_*PSTR + s1_)*2,                      \
                  &W[(size_t)(col0 + r1_)*256 + (k0) + s1_]);                  \
        asm volatile("cp.async.commit_group;");                                \
    } while (0)

#define GEMM_MMA_CHUNK(cur)                                                    \
    _Pragma("unroll")                                                          \
    for (int st = 0; st < 2; st++) {                                           \
        unsigned aF[2][4];                                                     \
        _Pragma("unroll")                                                      \
        for (int rc = 0; rc < 2; rc++) {                                       \
            int m = wm * 32 + rc * 16;                                         \
            aF[rc][0] = *(const unsigned*)&sX[cur][m + g][st*16 + 2*q];        \
            aF[rc][1] = *(const unsigned*)&sX[cur][m + g + 8][st*16 + 2*q];    \
            aF[rc][2] = *(const unsigned*)&sX[cur][m + g][st*16 + 2*q + 8];    \
            aF[rc][3] = *(const unsigned*)&sX[cur][m + g + 8][st*16 + 2*q + 8];\
        }                                                                      \
        _Pragma("unroll")                                                      \
        for (int nc = 0; nc < 8; nc++) {                                       \
            int n = wn * 64 + nc * 8 + g;                                      \
            unsigned b0 = *(const unsigned*)&sW[cur][n][st*16 + 2*q];          \
            unsigned b1 = *(const unsigned*)&sW[cur][n][st*16 + 2*q + 8];      \
            _Pragma("unroll")                                                  \
            for (int rc = 0; rc < 2; rc++)                                     \
                mma_f16(acc[rc][nc], aF[rc], b0, b1);                          \
        }                                                                      \
    }

__global__ __launch_bounds__(256) void qkv_gemm_kernel(
    const float* __restrict__ bq, const float* __restrict__ bk,
    const float* __restrict__ bv)
{
    const int p = blockIdx.z;
    const __half* X = (p < 2) ? g_xqk : g_xv;
    const __half* W = g_w + p * E_ * E_;
    const float* bias = (p == 0) ? bq : (p == 1) ? bk : bv;

    __shared__ __half sX[2][128][PSTR], sW[2][128][PSTR];

    const int tid  = threadIdx.x;
    const int wid  = tid >> 5;
    const int lane = tid & 31;
    const int g    = lane >> 2, q = lane & 3;
    const int wm   = wid >> 1, wn = wid & 1;

    const int row0 = blockIdx.x * 128;
    const int col0 = blockIdx.y * 128;

    const int r0_ = tid >> 2, s0_ = (tid & 3) * 8;
    const int r1_ = (tid + 256) >> 2, s1_ = ((tid + 256) & 3) * 8;
    const unsigned bX = (unsigned)__cvta_generic_to_shared(&sX[0][0][0]);
    const unsigned bW = (unsigned)__cvta_generic_to_shared(&sW[0][0][0]);

    float acc[2][8][4] = {};

    GEMM_STAGE(0, 0, X, W);
    #pragma unroll
    for (int kc = 0; kc < 8; kc++) {
        const int cur = kc & 1;
        if (kc + 1 < 8) GEMM_STAGE(cur ^ 1, (kc + 1) * 32, X, W);
        if (kc + 1 < 8) { asm volatile("cp.async.wait_group 1;"); }
        else            { asm volatile("cp.async.wait_group 0;"); }
        __syncthreads();
        GEMM_MMA_CHUNK(cur);
        __syncthreads();
    }

    // Epilogue: bias + scatter to fp16 per-head layouts
    #pragma unroll
    for (int nc = 0; nc < 8; nc++) {
        int col = col0 + wn * 64 + nc * 8 + 2 * q;
        float2 bv2 = *(const float2*)&bias[col];
        int h = col >> 5, d = col & 31;
        #pragma unroll
        for (int rc = 0; rc < 2; rc++) {
            int rowg = row0 + wm * 32 + rc * 16 + g;
            int bb = rowg >> 11;
            int t  = rowg & 2047;
            int bh = bb * H_ + h;
            float v0 = acc[rc][nc][0] + bv2.x;
            float v1 = acc[rc][nc][1] + bv2.y;
            float v2 = acc[rc][nc][2] + bv2.x;
            float v3 = acc[rc][nc][3] + bv2.y;
            if (p == 0) {
                *(unsigned*)&g_q[((size_t)(bh * T_ + t)) * D_ + d]     = packhf(v0 * SCALING_L2E, v1 * SCALING_L2E);
                *(unsigned*)&g_q[((size_t)(bh * T_ + t + 8)) * D_ + d] = packhf(v2 * SCALING_L2E, v3 * SCALING_L2E);
            } else if (p == 1) {
                *(unsigned*)&g_k[((size_t)(bh * T_ + t)) * D_ + d]     = packhf(v0, v1);
                *(unsigned*)&g_k[((size_t)(bh * T_ + t + 8)) * D_ + d] = packhf(v2, v3);
            } else {
                __half* vd0 = g_vt + ((size_t)(bh * D_ + d)) * T_;
                __half* vd1 = g_vt + ((size_t)(bh * D_ + d + 1)) * T_;
                vd0[t]     = __float2half(v0);
                vd1[t]     = __float2half(v1);
                vd0[t + 8] = __float2half(v2);
                vd1[t + 8] = __float2half(v3);
            }
        }
    }
}

__global__ __launch_bounds__(256) void out_gemm_kernel(
    const float* __restrict__ bo, float* __restrict__ out)
{
    const __half* X = g_ao;
    const __half* W = g_w + 3 * E_ * E_;

    __shared__ __half sX[2][128][PSTR], sW[2][128][PSTR];

    const int tid  = threadIdx.x;
    const int wid  = tid >> 5;
    const int lane = tid & 31;
    const int g    = lane >> 2, q = lane & 3;
    const int wm   = wid >> 1, wn = wid & 1;

    const int row0 = blockIdx.x * 128;
    const int col0 = blockIdx.y * 128;

    const int r0_ = tid >> 2, s0_ = (tid & 3) * 8;
    const int r1_ = (tid + 256) >> 2, s1_ = ((tid + 256) & 3) * 8;
    const unsigned bX = (unsigned)__cvta_generic_to_shared(&sX[0][0][0]);
    const unsigned bW = (unsigned)__cvta_generic_to_shared(&sW[0][0][0]);

    float acc[2][8][4] = {};

    GEMM_STAGE(0, 0, X, W);
    #pragma unroll
    for (int kc = 0; kc < 8; kc++) {
        const int cur = kc & 1;
        if (kc + 1 < 8) GEMM_STAGE(cur ^ 1, (kc + 1) * 32, X, W);
        if (kc + 1 < 8) { asm volatile("cp.async.wait_group 1;"); }
        else            { asm volatile("cp.async.wait_group 0;"); }
        __syncthreads();
        GEMM_MMA_CHUNK(cur);
        __syncthreads();
    }

    #pragma unroll
    for (int nc = 0; nc < 8; nc++) {
        int col = col0 + wn * 64 + nc * 8 + 2 * q;
        float2 bv2 = *(const float2*)&bo[col];
        #pragma unroll
        for (int rc = 0; rc < 2; rc++) {
            int rowg = row0 + wm * 32 + rc * 16 + g;
            float2 o0; o0.x = acc[rc][nc][0] + bv2.x; o0.y = acc[rc][nc][1] + bv2.y;
            float2 o1; o1.x = acc[rc][nc][2] + bv2.x; o1.y = acc[rc][nc][3] + bv2.y;
            *(float2*)&out[(size_t)rowg * 256 + col]       = o0;
            *(float2*)&out[(size_t)(rowg + 8) * 256 + col] = o1;
        }
    }
}

// ---------------------------------------------------------------------------
// Flash attention, full fp16: fp16 mma for QK and PV, exp via ex2.approx.f16x2
// (one MUFU op per 2 exps; results feed PV A-fragments directly).
#define KS_STRIDE 40   // halves
#define VS_STRIDE 72   // halves
__global__ __launch_bounds__(128, 5) void attn_mma_kernel(const float* __restrict__ mask)
{
    __shared__ __half Ksh[2][64][KS_STRIDE];
    __shared__ __half Vsh[2][32][VS_STRIDE];

    const int tid  = threadIdx.x;
    const int lane = tid & 31;
    const int w    = tid >> 5;
    const int g    = lane >> 2;
    const int q    = lane & 3;

    const int bh = blockIdx.y;
    const int b  = bh >> 3, h = bh & 7;
    const int m0 = blockIdx.x * 64;
    const int mrow = m0 + w * 16 + g;

    const __half* kbase = g_k  + (size_t)bh * T_ * D_;
    const __half* vbase = g_vt + (size_t)bh * D_ * T_;
    const float* mrow0 = mask + (size_t)b * T_ * T_ + (size_t)mrow * T_;
    const float* mrow1 = mrow0 + 8 * T_;
    const int flag = g_maskflag;

    const int krow = tid >> 2, kc = (tid & 3) * 8;
    const int krow2 = (tid + 128) >> 2, kc2 = ((tid + 128) & 3) * 8;
    const int vrow = tid >> 3, vc = (tid & 7) * 8;
    const int vrow2 = (tid + 128) >> 3, vc2 = ((tid + 128) & 7) * 8;

    const unsigned ksh0 = (unsigned)__cvta_generic_to_shared(&Ksh[0][0][0]);
    const unsigned vsh0 = (unsigned)__cvta_generic_to_shared(&Vsh[0][0][0]);
    const unsigned KBUF = 64 * KS_STRIDE * 2;
    const unsigned VBUF = 32 * VS_STRIDE * 2;
    const unsigned kst0 = ksh0 + (krow  * KS_STRIDE + kc ) * 2;
    const unsigned kst1 = ksh0 + (krow2 * KS_STRIDE + kc2) * 2;
    const unsigned vst0 = vsh0 + (vrow  * VS_STRIDE + vc ) * 2;
    const unsigned vst1 = vsh0 + (vrow2 * VS_STRIDE + vc2) * 2;
    const unsigned kfa = ksh0 + ((lane & 7) * KS_STRIDE + (lane >> 3) * 8) * 2;
    const unsigned vfa = vsh0 + ((lane & 7) * VS_STRIDE + (lane >> 3) * 8) * 2;

    unsigned aQ[2][4];
    {
        const __half* qb = g_q + ((size_t)(bh * T_ + m0 + w * 16)) * D_;
        #pragma unroll
        for (int s = 0; s < 2; s++) {
            aQ[s][0] = *(const unsigned*)&qb[g * D_ + s * 16 + 2 * q];
            aQ[s][1] = *(const unsigned*)&qb[(g + 8) * D_ + s * 16 + 2 * q];
            aQ[s][2] = *(const unsigned*)&qb[g * D_ + s * 16 + 2 * q + 8];
            aQ[s][3] = *(const unsigned*)&qb[(g + 8) * D_ + s * 16 + 2 * q + 8];
        }
    }

    float o[4][4] = {};
    float lr0 = 0.f, lr1 = 0.f;

    cpasync16(kst0, &kbase[(size_t)krow  * D_ + kc]);
    cpasync16(kst1, &kbase[(size_t)krow2 * D_ + kc2]);
    cpasync16(vst0, &vbase[(size_t)vrow  * T_ + vc]);
    cpasync16(vst1, &vbase[(size_t)vrow2 * T_ + vc2]);
    asm volatile("cp.async.commit_group;");
    asm volatile("cp.async.wait_group 0;");
    __syncthreads();

    const int NT = T_ / 64;
    for (int it = 0; it < NT; it++) {
        const int cur = it & 1;
        const unsigned nxtoff = (cur ^ 1);
        const int n0 = it * 64;

        if (it + 1 < NT) {
            int nn = n0 + 64;
            cpasync16(kst0 + nxtoff * KBUF, &kbase[(size_t)(nn + krow)  * D_ + kc]);
            cpasync16(kst1 + nxtoff * KBUF, &kbase[(size_t)(nn + krow2) * D_ + kc2]);
            cpasync16(vst0 + nxtoff * VBUF, &vbase[(size_t)vrow  * T_ + nn + vc]);
            cpasync16(vst1 + nxtoff * VBUF, &vbase[(size_t)vrow2 * T_ + nn + vc2]);
            asm volatile("cp.async.commit_group;");
        }

        unsigned pA[4][4];
        float s[4][4];

        // ===== Half A: keys n0..n0+31 =====
        if (flag) {
            #pragma unroll
            for (int j = 0; j < 4; j++) {
                float2 a01 = *(const float2*)(mrow0 + n0 + j * 8 + 2 * q);
                float2 a23 = *(const float2*)(mrow1 + n0 + j * 8 + 2 * q);
                s[j][0] = a01.x * LOG2E; s[j][1] = a01.y * LOG2E;
                s[j][2] = a23.x * LOG2E; s[j][3] = a23.y * LOG2E;
            }
        } else {
            #pragma unroll
            for (int j = 0; j < 4; j++)
                #pragma unroll
                for (int c = 0; c < 4; c++) s[j][c] = 0.f;
        }
        #pragma unroll
        for (int j = 0; j < 4; j++) {
            unsigned b0, b1, b2, b3;
            ldsm4(b0, b1, b2, b3, kfa + cur * KBUF + j * 8 * KS_STRIDE * 2);
            mma_f16(s[j], aQ[0], b0, b1);
            mma_f16(s[j], aQ[1], b2, b3);
        }
        // exp2 in packed fp16; results are PV A-fragments directly
        #pragma unroll
        for (int j = 0; j < 4; j++) {
            unsigned pa = ex2h2(packhf(s[j][0], s[j][1]));   // row g pair
            unsigned pb = ex2h2(packhf(s[j][2], s[j][3]));   // row g+8 pair
            int kt = j >> 1, sl = (j & 1) * 2;
            pA[kt][sl + 0] = pa;
            pA[kt][sl + 1] = pb;
            float2 fa = __half22float2(*(__half2*)&pa);
            float2 fb = __half22float2(*(__half2*)&pb);
            lr0 += fa.x + fa.y;
            lr1 += fb.x + fb.y;
        }

        // ===== Half B scores: keys n0+32..n0+63 =====
        if (flag) {
            #pragma unroll
            for (int j = 0; j < 4; j++) {
                float2 a01 = *(const float2*)(mrow0 + n0 + 32 + j * 8 + 2 * q);
                float2 a23 = *(const float2*)(mrow1 + n0 + 32 + j * 8 + 2 * q);
                s[j][0] = a01.x * LOG2E; s[j][1] = a01.y * LOG2E;
                s[j][2] = a23.x * LOG2E; s[j][3] = a23.y * LOG2E;
            }
        } else {
            #pragma unroll
            for (int j = 0; j < 4; j++)
                #pragma unroll
                for (int c = 0; c < 4; c++) s[j][c] = 0.f;
        }
        #pragma unroll
        for (int j = 0; j < 4; j++) {
            unsigned b0, b1, b2, b3;
            ldsm4(b0, b1, b2, b3, kfa + cur * KBUF + (j + 4) * 8 * KS_STRIDE * 2);
            mma_f16(s[j], aQ[0], b0, b1);
            mma_f16(s[j], aQ[1], b2, b3);
        }

        // ===== PV half A (tensor) overlaps half-B exp (MUFU) =====
        #pragma unroll
        for (int t = 0; t < 4; t++) {
            unsigned v0, v1, v2, v3;
            ldsm4(v0, v1, v2, v3, vfa + cur * VBUF + t * 8 * VS_STRIDE * 2);
            mma_f16(o[t], pA[0], v0, v1);
            mma_f16(o[t], pA[1], v2, v3);
        }

        // ===== Half B exp =====
        #pragma unroll
        for (int j = 0; j < 4; j++) {
            unsigned pa = ex2h2(packhf(s[j][0], s[j][1]));
            unsigned pb = ex2h2(packhf(s[j][2], s[j][3]));
            int kt = 2 + (j >> 1), sl = (j & 1) * 2;
            pA[kt][sl + 0] = pa;
            pA[kt][sl + 1] = pb;
            float2 fa = __half22float2(*(__half2*)&pa);
            float2 fb = __half22float2(*(__half2*)&pb);
            lr0 += fa.x + fa.y;
            lr1 += fb.x + fb.y;
        }

        // ===== PV half B =====
        #pragma unroll
        for (int t = 0; t < 4; t++) {
            unsigned v4, v5, v6, v7;
            ldsm4(v4, v5, v6, v7, vfa + cur * VBUF + t * 8 * VS_STRIDE * 2 + 32 * 2);
            mma_f16(o[t], pA[2], v4, v5);
            mma_f16(o[t], pA[3], v6, v7);
        }

        if (it + 1 < NT) {
            asm volatile("cp.async.wait_group 0;");
            __syncthreads();
        }
    }

    lr0 += __shfl_xor_sync(0xffffffffu, lr0, 1);
    lr0 += __shfl_xor_sync(0xffffffffu, lr0, 2);
    lr1 += __shfl_xor_sync(0xffffffffu, lr1, 1);
    lr1 += __shfl_xor_sync(0xffffffffu, lr1, 2);

    // Epilogue: normalize, write fp16 to g_ao
    float inv0 = 1.f / lr0, inv1 = 1.f / lr1;
    size_t base0 = ((size_t)(b * T_ + mrow)) * E_ + h * 32;
    size_t base1 = base0 + 8 * E_;
    #pragma unroll
    for (int t = 0; t < 4; t++) {
        int dd = t * 8 + 2 * q;
        *(unsigned*)&g_ao[base0 + dd] = packhf(o[t][0] * inv0, o[t][1] * inv0);
        *(unsigned*)&g_ao[base1 + dd] = packhf(o[t][2] * inv1, o[t][3] * inv1);
    }
}

// ---------------------------------------------------------------------------
extern "C" void kernel_launch(void* const* d_in, const int* in_sizes, int n_in,
                              void* d_out, int out_size)
{
    const float* hs   = (const float*)d_in[0];
    const float* pos  = (const float*)d_in[1];
    const float* mask = (const float*)d_in[2];
    const float* Wq   = (const float*)d_in[3];
    const float* bq   = (const float*)d_in[4];
    const float* Wk   = (const float*)d_in[5];
    const float* bk   = (const float*)d_in[6];
    const float* Wv   = (const float*)d_in[7];
    const float* bv   = (const float*)d_in[8];
    const float* Wo   = (const float*)d_in[9];
    const float* bo   = (const float*)d_in[10];
    float* out = (float*)d_out;

    flag_init_kernel<<<1, 1>>>();
    mask_scan_kernel<<<1024, 256>>>(mask, (B_ * T_ * T_) / 4);

    split_x_kernel<<<(B_ * T_ * E_) / 4 / 256, 256>>>(hs, pos);
    split_w_kernel<<<dim3((E_ * E_) / 4 / 256, 4), 256>>>(Wq, Wk, Wv, Wo);

    dim3 pgrid(B_ * T_ / 128, E_ / 128, 3);
    qkv_gemm_kernel<<<pgrid, 256>>>(bq, bk, bv);

    dim3 agrid(T_ / 64, B_ * H_);
    attn_mma_kernel<<<agrid, 128>>>(mask);

    dim3 ogrid(B_ * T_ / 128, E_ / 128);
    out_gemm_kernel<<<ogrid, 256>>>(bo, out);
}